// round 1
// baseline (speedup 1.0000x reference)
#include <cuda_runtime.h>

#define MARGIN 0.3f
#define DIM 128
#define MAXN 4096
#define BM 64
#define BN 64
#define BK 16
#define SPAD 68   // BK-major tile row pitch (floats): keeps LDS.128 aligned, low-conflict STS

__device__ float g_n1[MAXN];
__device__ float g_n2[MAXN];
__device__ float g_C[MAXN];
__device__ unsigned int g_rowmax[MAXN];
__device__ float g_partial[(MAXN / BM) * (MAXN / BN)];

// --- prep: row norms, C_i = dist_ap - ||p1_i||^2 + margin, zero rowmax ---
__global__ void prep_kernel(const float* __restrict__ p1,
                            const float* __restrict__ p2, int n) {
    int row = blockIdx.x * 8 + (threadIdx.x >> 5);
    int lane = threadIdx.x & 31;
    if (row >= n) return;
    const float4* a = (const float4*)(p1 + (size_t)row * DIM);
    const float4* b = (const float4*)(p2 + (size_t)row * DIM);
    float4 av = a[lane];
    float4 bv = b[lane];
    float n1 = av.x * av.x + av.y * av.y + av.z * av.z + av.w * av.w;
    float n2 = bv.x * bv.x + bv.y * bv.y + bv.z * bv.z + bv.w * bv.w;
    float dx = av.x - bv.x, dy = av.y - bv.y, dz = av.z - bv.z, dw = av.w - bv.w;
    float dap = dx * dx + dy * dy + dz * dz + dw * dw;
#pragma unroll
    for (int m = 16; m; m >>= 1) {
        n1 += __shfl_xor_sync(0xffffffffu, n1, m);
        n2 += __shfl_xor_sync(0xffffffffu, n2, m);
        dap += __shfl_xor_sync(0xffffffffu, dap, m);
    }
    if (lane == 0) {
        g_n1[row] = n1;
        g_n2[row] = n2;
        g_C[row] = dap - n1 + MARGIN;
        g_rowmax[row] = 0u;
    }
}

// --- main: dual 64x64x128 fp32 GEMM tile + fused relu/max/sum epilogue ---
__global__ void __launch_bounds__(256, 4)
triplet_main_kernel(const float* __restrict__ p1,
                    const float* __restrict__ p2, int n) {
    __shared__ float As[BK][SPAD];
    __shared__ float B1s[BK][SPAD];
    __shared__ float B2s[BK][SPAD];

    const int bi = blockIdx.y;
    const int bj = blockIdx.x;
    const int tid = threadIdx.x;
    const int tx = tid & 15;
    const int ty = tid >> 4;

    float acc1[4][4];
    float acc2[4][4];
#pragma unroll
    for (int r = 0; r < 4; r++)
#pragma unroll
        for (int c = 0; c < 4; c++) { acc1[r][c] = 0.f; acc2[r][c] = 0.f; }

    const int lm = tid >> 2;          // 0..63 : tile row
    const int lk = (tid & 3) * 4;     // 0,4,8,12 : k offset within chunk

    const float* Ag  = p1 + (size_t)(bi * BM + lm) * DIM + lk;
    const float* B1g = p1 + (size_t)(bj * BN + lm) * DIM + lk;
    const float* B2g = p2 + (size_t)(bj * BN + lm) * DIM + lk;

#pragma unroll
    for (int kb = 0; kb < DIM; kb += BK) {
        float4 a  = *(const float4*)(Ag + kb);
        float4 b1 = *(const float4*)(B1g + kb);
        float4 b2 = *(const float4*)(B2g + kb);
        __syncthreads();   // prior-iteration reads done before overwrite
        As[lk + 0][lm] = a.x;  As[lk + 1][lm] = a.y;
        As[lk + 2][lm] = a.z;  As[lk + 3][lm] = a.w;
        B1s[lk + 0][lm] = b1.x; B1s[lk + 1][lm] = b1.y;
        B1s[lk + 2][lm] = b1.z; B1s[lk + 3][lm] = b1.w;
        B2s[lk + 0][lm] = b2.x; B2s[lk + 1][lm] = b2.y;
        B2s[lk + 2][lm] = b2.z; B2s[lk + 3][lm] = b2.w;
        __syncthreads();
#pragma unroll
        for (int k = 0; k < BK; k++) {
            float4 af  = *(const float4*)&As[k][ty * 4];
            float4 bf1 = *(const float4*)&B1s[k][tx * 4];
            float4 bf2 = *(const float4*)&B2s[k][tx * 4];
            float ar[4] = {af.x, af.y, af.z, af.w};
            float b1r[4] = {bf1.x, bf1.y, bf1.z, bf1.w};
            float b2r[4] = {bf2.x, bf2.y, bf2.z, bf2.w};
#pragma unroll
            for (int r = 0; r < 4; r++) {
#pragma unroll
                for (int c = 0; c < 4; c++) {
                    acc1[r][c] = fmaf(ar[r], b1r[c], acc1[r][c]);
                    acc2[r][c] = fmaf(ar[r], b2r[c], acc2[r][c]);
                }
            }
        }
    }

    // ---- epilogue ----
    const int ibase = bi * BM + ty * 4;
    const int jbase = bj * BN + tx * 4;
    float Cr[4], n1c[4], n2c[4];
#pragma unroll
    for (int r = 0; r < 4; r++) Cr[r] = g_C[ibase + r];
#pragma unroll
    for (int c = 0; c < 4; c++) { n1c[c] = g_n1[jbase + c]; n2c[c] = g_n2[jbase + c]; }

    float sum = 0.f;
    float rmax[4] = {0.f, 0.f, 0.f, 0.f};
#pragma unroll
    for (int r = 0; r < 4; r++) {
#pragma unroll
        for (int c = 0; c < 4; c++) {
            float v1 = fmaxf(Cr[r] - n1c[c] + 2.f * acc1[r][c], 0.f);
            float v2 = fmaxf(Cr[r] - n2c[c] + 2.f * acc2[r][c], 0.f);
            if (ibase + r == jbase + c) { v1 = 0.f; v2 = 0.f; }
            sum += v1 + v2;
            rmax[r] = fmaxf(rmax[r], fmaxf(v1, v2));
        }
    }

    // per-row max across the 16 tx lanes (xor<16 stays within the half-warp row group)
#pragma unroll
    for (int m = 8; m; m >>= 1) {
#pragma unroll
        for (int r = 0; r < 4; r++)
            rmax[r] = fmaxf(rmax[r], __shfl_xor_sync(0xffffffffu, rmax[r], m));
    }
    if (tx == 0) {
#pragma unroll
        for (int r = 0; r < 4; r++)
            atomicMax(&g_rowmax[ibase + r], __float_as_uint(rmax[r]));  // vals >= 0: bit order == float order
    }

    // block sum -> deterministic per-block partial
#pragma unroll
    for (int m = 16; m; m >>= 1) sum += __shfl_xor_sync(0xffffffffu, sum, m);
    __shared__ float ssum[8];
    if ((tid & 31) == 0) ssum[tid >> 5] = sum;
    __syncthreads();
    if (tid == 0) {
        float t = 0.f;
#pragma unroll
        for (int w = 0; w < 8; w++) t += ssum[w];
        g_partial[blockIdx.y * gridDim.x + blockIdx.x] = t;
    }
}

// --- final: deterministic double-precision reduction of rowmax + partials ---
__global__ void final_kernel(float* __restrict__ out, int n, int nblocks) {
    __shared__ double s1[256];
    __shared__ double s2[256];
    int tid = threadIdx.x;
    double smax = 0.0, ssum = 0.0;
    for (int i = tid; i < n; i += 256) smax += (double)__uint_as_float(g_rowmax[i]);
    for (int i = tid; i < nblocks; i += 256) ssum += (double)g_partial[i];
    s1[tid] = smax;
    s2[tid] = ssum;
    __syncthreads();
    for (int s = 128; s; s >>= 1) {
        if (tid < s) { s1[tid] += s1[tid + s]; s2[tid] += s2[tid + s]; }
        __syncthreads();
    }
    if (tid == 0) {
        out[0] = (float)(s1[0] / (double)n);
        out[1] = (float)(s2[0] / (2.0 * (double)n * (double)(n - 1)));
    }
}

extern "C" void kernel_launch(void* const* d_in, const int* in_sizes, int n_in,
                              void* d_out, int out_size) {
    const float* p1 = (const float*)d_in[0];
    const float* p2 = (const float*)d_in[1];
    float* out = (float*)d_out;
    const int n = in_sizes[0] / DIM;  // 4096

    prep_kernel<<<(n + 7) / 8, 256>>>(p1, p2, n);

    dim3 grid(n / BN, n / BM);
    triplet_main_kernel<<<grid, 256>>>(p1, p2, n);

    final_kernel<<<1, 256>>>(out, n, (n / BM) * (n / BN));
}

// round 3
// speedup vs baseline: 1.7799x; 1.7799x over previous
#include <cuda_runtime.h>
#include <cuda_bf16.h>
#include <cstdint>

#define MARGIN 0.3f
#define DIM  128
#define TILE 128
#define MAXN 4096

// ---- dynamic smem layout (bytes) ----
#define SM_SN1  0
#define SM_SN2  512
#define SM_SC   1024
#define SM_RMAX 1536               // 128 uints
#define SM_SSUM 2048               // 8 floats
#define SM_OPS  4096               // operand tiles, 1024-aligned
#define OP_BYTES 32768             // 128 rows x 128 bf16 (two 16KB 64-col halves, SW128)
#define SMEM_TOTAL (SM_OPS + 6*OP_BYTES)
// tile order: A_HI, A_LO, B1_HI, B1_LO, B2_HI, B2_LO

__device__ unsigned int g_rowmax[MAXN];   // zeroed at load; final kernel re-zeros
__device__ float g_partial[(MAXN/TILE)*(MAXN/TILE)];

__device__ __forceinline__ uint32_t smem_u32(const void* p) {
    uint32_t a;
    asm("{ .reg .u64 t; cvta.to.shared.u64 t, %1; cvt.u32.u64 %0, t; }" : "=r"(a) : "l"(p));
    return a;
}

// swizzled byte address of (row, kcol) within a 128x128 bf16 tile
__device__ __forceinline__ uint32_t taddr(uint32_t base, int row, int kcol) {
    int b = row * 128 + (kcol & 63) * 2;
    b ^= (b >> 3) & 0x70;
    return base + ((kcol >> 6) << 14) + b;
}

__device__ __forceinline__ void ldsm4(uint32_t addr, uint32_t r[4]) {
    asm volatile("ldmatrix.sync.aligned.m8n8.x4.shared.b16 {%0,%1,%2,%3}, [%4];"
                 : "=r"(r[0]), "=r"(r[1]), "=r"(r[2]), "=r"(r[3]) : "r"(addr));
}

#define MMA(d, a, b)                                                               \
    asm volatile("mma.sync.aligned.m16n8k16.row.col.f32.bf16.bf16.f32 "            \
                 "{%0,%1,%2,%3},{%4,%5,%6,%7},{%8,%9},{%0,%1,%2,%3};"              \
                 : "+f"((d)[0]), "+f"((d)[1]), "+f"((d)[2]), "+f"((d)[3])          \
                 : "r"((a)[0]), "r"((a)[1]), "r"((a)[2]), "r"((a)[3]),             \
                   "r"((b)[0]), "r"((b)[1]))

union BU { __nv_bfloat162 b; uint32_t u; };

__global__ void __launch_bounds__(256, 1)
triplet_mma_kernel(const float* __restrict__ p1, const float* __restrict__ p2, int n) {
    extern __shared__ char smem[];
    const uint32_t sbase = smem_u32(smem);
    const int tid = threadIdx.x;
    const int wid = tid >> 5;
    const int l   = tid & 31;
    const int bj = blockIdx.x, bi = blockIdx.y;

    float* sn1 = (float*)(smem + SM_SN1);
    float* sn2 = (float*)(smem + SM_SN2);
    float* sC  = (float*)(smem + SM_SC);
    unsigned int* srmax = (unsigned int*)(smem + SM_RMAX);
    float* ssum = (float*)(smem + SM_SSUM);

    if (tid < 128) srmax[tid] = 0u;

    // ---- load fp32, split bf16 hi/lo into swizzled smem; fused row reductions ----
    {
        const float* srcA  = p1 + (size_t)(bi * TILE) * DIM;
        const float* auxA  = p2 + (size_t)(bi * TILE) * DIM;   // for dist_ap
        const float* srcB1 = p1 + (size_t)(bj * TILE) * DIM;
        const float* srcB2 = p2 + (size_t)(bj * TILE) * DIM;

#pragma unroll 1
        for (int it = 0; it < 16; it++) {
            int idx = it * 256 + tid;
            int row = idx >> 5;            // each warp covers one full row per step
            int k = (idx & 31) * 4;
            int woff = row * 128 + (k & 63) * 2;
            int sw = (woff ^ ((woff >> 3) & 0x70)) + ((k >> 6) << 14);

            // A tile (p1 rows of bi) + dist_ap
            float4 a = *(const float4*)(srcA + row * DIM + k);
            float4 b = *(const float4*)(auxA + row * DIM + k);
            BU h0, h1, l0, l1;
            h0.b = __floats2bfloat162_rn(a.x, a.y);
            h1.b = __floats2bfloat162_rn(a.z, a.w);
            l0.b = __floats2bfloat162_rn(a.x - __bfloat162float(h0.b.x),
                                         a.y - __bfloat162float(h0.b.y));
            l1.b = __floats2bfloat162_rn(a.z - __bfloat162float(h1.b.x),
                                         a.w - __bfloat162float(h1.b.y));
            *(uint2*)(smem + SM_OPS + 0 * OP_BYTES + sw) = make_uint2(h0.u, h1.u);
            *(uint2*)(smem + SM_OPS + 1 * OP_BYTES + sw) = make_uint2(l0.u, l1.u);
            float sq = a.x*a.x + a.y*a.y + a.z*a.z + a.w*a.w;
            float dx = a.x-b.x, dy = a.y-b.y, dz = a.z-b.z, dw = a.w-b.w;
            float dq = dx*dx + dy*dy + dz*dz + dw*dw;
#pragma unroll
            for (int m = 16; m; m >>= 1) {
                sq += __shfl_xor_sync(0xffffffffu, sq, m);
                dq += __shfl_xor_sync(0xffffffffu, dq, m);
            }
            if (l == 0) sC[row] = dq - sq + MARGIN;

            // B1 tile (p1 rows of bj)
            a = *(const float4*)(srcB1 + row * DIM + k);
            h0.b = __floats2bfloat162_rn(a.x, a.y);
            h1.b = __floats2bfloat162_rn(a.z, a.w);
            l0.b = __floats2bfloat162_rn(a.x - __bfloat162float(h0.b.x),
                                         a.y - __bfloat162float(h0.b.y));
            l1.b = __floats2bfloat162_rn(a.z - __bfloat162float(h1.b.x),
                                         a.w - __bfloat162float(h1.b.y));
            *(uint2*)(smem + SM_OPS + 2 * OP_BYTES + sw) = make_uint2(h0.u, h1.u);
            *(uint2*)(smem + SM_OPS + 3 * OP_BYTES + sw) = make_uint2(l0.u, l1.u);
            sq = a.x*a.x + a.y*a.y + a.z*a.z + a.w*a.w;
#pragma unroll
            for (int m = 16; m; m >>= 1) sq += __shfl_xor_sync(0xffffffffu, sq, m);
            if (l == 0) sn1[row] = sq;

            // B2 tile (p2 rows of bj)
            a = *(const float4*)(srcB2 + row * DIM + k);
            h0.b = __floats2bfloat162_rn(a.x, a.y);
            h1.b = __floats2bfloat162_rn(a.z, a.w);
            l0.b = __floats2bfloat162_rn(a.x - __bfloat162float(h0.b.x),
                                         a.y - __bfloat162float(h0.b.y));
            l1.b = __floats2bfloat162_rn(a.z - __bfloat162float(h1.b.x),
                                         a.w - __bfloat162float(h1.b.y));
            *(uint2*)(smem + SM_OPS + 4 * OP_BYTES + sw) = make_uint2(h0.u, h1.u);
            *(uint2*)(smem + SM_OPS + 5 * OP_BYTES + sw) = make_uint2(l0.u, l1.u);
            sq = a.x*a.x + a.y*a.y + a.z*a.z + a.w*a.w;
#pragma unroll
            for (int m = 16; m; m >>= 1) sq += __shfl_xor_sync(0xffffffffu, sq, m);
            if (l == 0) sn2[row] = sq;
        }
    }
    __syncthreads();

    // ---- warp tiling: 2 (M) x 4 (N) warps, warp tile 64x32 ----
    const int wm = wid & 1;
    const int wn = wid >> 1;
    const uint32_t AHI = sbase + SM_OPS + 0 * OP_BYTES;
    const uint32_t ALO = sbase + SM_OPS + 1 * OP_BYTES;
    const bool diag = (bi == bj);

    const int qr = l >> 2;            // 0..7 row within frag
    const int qc = (l & 3) * 2;       // col pair base within n8

    float sum = 0.f;

#pragma unroll 1
    for (int pass = 0; pass < 2; pass++) {
        const uint32_t BHI = sbase + SM_OPS + (2 + 2 * pass) * OP_BYTES;
        const uint32_t BLO = BHI + OP_BYTES;

        float acc[4][4][4];
#pragma unroll
        for (int mf = 0; mf < 4; mf++)
#pragma unroll
            for (int nf = 0; nf < 4; nf++)
#pragma unroll
                for (int e = 0; e < 4; e++) acc[mf][nf][e] = 0.f;

        const int arow = wm * 64 + (l & 7) + ((l >> 3) & 1) * 8;
        const int akoff = (l >> 4) * 8;
        const int brow = wn * 32 + (l & 7) + ((l >> 4) << 3);
        const int bkoff = ((l >> 3) & 1) * 8;

#pragma unroll 2
        for (int ks = 0; ks < 8; ks++) {
            const int k0 = ks * 16;
            uint32_t ah[4][4], al[4][4];
#pragma unroll
            for (int mf = 0; mf < 4; mf++) {
                ldsm4(taddr(AHI, arow + mf * 16, k0 + akoff), ah[mf]);
                ldsm4(taddr(ALO, arow + mf * 16, k0 + akoff), al[mf]);
            }
            uint32_t bh[4][2], bl[4][2];
#pragma unroll
            for (int np = 0; np < 2; np++) {
                uint32_t t[4];
                ldsm4(taddr(BHI, brow + np * 16, k0 + bkoff), t);
                bh[2*np][0] = t[0]; bh[2*np][1] = t[1];
                bh[2*np+1][0] = t[2]; bh[2*np+1][1] = t[3];
                ldsm4(taddr(BLO, brow + np * 16, k0 + bkoff), t);
                bl[2*np][0] = t[0]; bl[2*np][1] = t[1];
                bl[2*np+1][0] = t[2]; bl[2*np+1][1] = t[3];
            }
#pragma unroll
            for (int mf = 0; mf < 4; mf++)
#pragma unroll
                for (int nf = 0; nf < 4; nf++) {
                    MMA(acc[mf][nf], ah[mf], bh[nf]);
                    MMA(acc[mf][nf], ah[mf], bl[nf]);
                    MMA(acc[mf][nf], al[mf], bh[nf]);
                }
        }

        // ---- epilogue for this accumulator ----
        const float* snn = pass ? sn2 : sn1;
        float Cr[4][2], nc[4][2];
#pragma unroll
        for (int mf = 0; mf < 4; mf++) {
            int r0 = wm * 64 + mf * 16 + qr;
            Cr[mf][0] = sC[r0];
            Cr[mf][1] = sC[r0 + 8];
        }
#pragma unroll
        for (int nf = 0; nf < 4; nf++) {
            int c0 = wn * 32 + nf * 8 + qc;
            nc[nf][0] = snn[c0];
            nc[nf][1] = snn[c0 + 1];
        }
        float rmax[4][2];
#pragma unroll
        for (int mf = 0; mf < 4; mf++) { rmax[mf][0] = 0.f; rmax[mf][1] = 0.f; }

#pragma unroll
        for (int mf = 0; mf < 4; mf++)
#pragma unroll
            for (int nf = 0; nf < 4; nf++)
#pragma unroll
                for (int e = 0; e < 4; e++) {
                    int rr = e >> 1, cc = e & 1;
                    float v = fmaxf(Cr[mf][rr] - nc[nf][cc] + 2.f * acc[mf][nf][e], 0.f);
                    if (diag) {
                        int rl = wm * 64 + mf * 16 + qr + rr * 8;
                        int cl = wn * 32 + nf * 8 + qc + cc;
                        if (rl == cl) v = 0.f;
                    }
                    sum += v;
                    rmax[mf][rr] = fmaxf(rmax[mf][rr], v);
                }
        // reduce row-max over the 4 lanes sharing each row
#pragma unroll
        for (int m = 1; m <= 2; m <<= 1)
#pragma unroll
            for (int mf = 0; mf < 4; mf++) {
                rmax[mf][0] = fmaxf(rmax[mf][0], __shfl_xor_sync(0xffffffffu, rmax[mf][0], m));
                rmax[mf][1] = fmaxf(rmax[mf][1], __shfl_xor_sync(0xffffffffu, rmax[mf][1], m));
            }
        if ((l & 3) == 0) {
#pragma unroll
            for (int mf = 0; mf < 4; mf++) {
                atomicMax(&srmax[wm * 64 + mf * 16 + qr],     __float_as_uint(rmax[mf][0]));
                atomicMax(&srmax[wm * 64 + mf * 16 + qr + 8], __float_as_uint(rmax[mf][1]));
            }
        }
    }

    __syncthreads();
    if (tid < 128)
        atomicMax(&g_rowmax[bi * TILE + tid], srmax[tid]);   // vals >= 0: uint order == float order

#pragma unroll
    for (int m = 16; m; m >>= 1) sum += __shfl_xor_sync(0xffffffffu, sum, m);
    if (l == 0) ssum[wid] = sum;
    __syncthreads();
    if (tid == 0) {
        float t = 0.f;
#pragma unroll
        for (int w = 0; w < 8; w++) t += ssum[w];
        g_partial[bi * gridDim.x + bj] = t;
    }
}

// ---- final deterministic reduction; re-zeros g_rowmax for graph replay ----
__global__ void final_kernel(float* __restrict__ out, int n, int nblocks) {
    __shared__ double s1[256];
    __shared__ double s2[256];
    int tid = threadIdx.x;
    double smax = 0.0, ssumd = 0.0;
    for (int i = tid; i < n; i += 256) {
        smax += (double)__uint_as_float(g_rowmax[i]);
        g_rowmax[i] = 0u;
    }
    for (int i = tid; i < nblocks; i += 256) ssumd += (double)g_partial[i];
    s1[tid] = smax; s2[tid] = ssumd;
    __syncthreads();
    for (int s = 128; s; s >>= 1) {
        if (tid < s) { s1[tid] += s1[tid + s]; s2[tid] += s2[tid + s]; }
        __syncthreads();
    }
    if (tid == 0) {
        out[0] = (float)(s1[0] / (double)n);
        out[1] = (float)(s2[0] / (2.0 * (double)n * (double)(n - 1)));
    }
}

extern "C" void kernel_launch(void* const* d_in, const int* in_sizes, int n_in,
                              void* d_out, int out_size) {
    const float* p1 = (const float*)d_in[0];
    const float* p2 = (const float*)d_in[1];
    float* out = (float*)d_out;
    const int n = in_sizes[0] / DIM;          // 4096
    const int nt = n / TILE;                  // 32

    cudaFuncSetAttribute(triplet_mma_kernel,
                         cudaFuncAttributeMaxDynamicSharedMemorySize, SMEM_TOTAL);

    dim3 grid(nt, nt);
    triplet_mma_kernel<<<grid, 256, SMEM_TOTAL>>>(p1, p2, n);
    final_kernel<<<1, 256>>>(out, n, nt * nt);
}

// round 4
// speedup vs baseline: 1.9579x; 1.1000x over previous
#include <cuda_runtime.h>
#include <cuda_bf16.h>
#include <cstdint>

#define MARGIN 0.3f
#define DIM  128
#define TILE 128
#define MAXN 4096

// ---- dynamic smem layout (bytes) ----
#define SM_SN1  0
#define SM_SN2  512
#define SM_SC   1024
#define SM_RMAX 1536               // 128 uints
#define SM_SSUM 2048               // 16 floats
#define SM_OPS  4096               // operand tiles, 1024-aligned
#define OP_BYTES 32768             // 128 rows x 128 bf16 (two 16KB 64-col halves, SW128)
#define SMEM_TOTAL (SM_OPS + 6*OP_BYTES)
// tile order: A_HI, A_LO, B1_HI, B1_LO, B2_HI, B2_LO

__device__ unsigned int g_rowmax[MAXN];   // zeroed at load; final kernel re-zeros
__device__ float g_partial[(MAXN/TILE)*(MAXN/TILE)];

__device__ __forceinline__ uint32_t smem_u32(const void* p) {
    uint32_t a;
    asm("{ .reg .u64 t; cvta.to.shared.u64 t, %1; cvt.u32.u64 %0, t; }" : "=r"(a) : "l"(p));
    return a;
}

// swizzled byte address of (row, kcol) within a 128x128 bf16 tile
__device__ __forceinline__ uint32_t taddr(uint32_t base, int row, int kcol) {
    int b = row * 128 + (kcol & 63) * 2;
    b ^= (b >> 3) & 0x70;
    return base + ((kcol >> 6) << 14) + b;
}

__device__ __forceinline__ void ldsm4(uint32_t addr, uint32_t r[4]) {
    asm volatile("ldmatrix.sync.aligned.m8n8.x4.shared.b16 {%0,%1,%2,%3}, [%4];"
                 : "=r"(r[0]), "=r"(r[1]), "=r"(r[2]), "=r"(r[3]) : "r"(addr));
}

#define MMA(d, a, b)                                                               \
    asm volatile("mma.sync.aligned.m16n8k16.row.col.f32.bf16.bf16.f32 "            \
                 "{%0,%1,%2,%3},{%4,%5,%6,%7},{%8,%9},{%0,%1,%2,%3};"              \
                 : "+f"((d)[0]), "+f"((d)[1]), "+f"((d)[2]), "+f"((d)[3])          \
                 : "r"((a)[0]), "r"((a)[1]), "r"((a)[2]), "r"((a)[3]),             \
                   "r"((b)[0]), "r"((b)[1]))

union BU { __nv_bfloat162 b; uint32_t u; };

__global__ void __launch_bounds__(512, 1)
triplet_mma_kernel(const float* __restrict__ p1, const float* __restrict__ p2, int n) {
    extern __shared__ char smem[];
    const uint32_t sbase = smem_u32(smem);
    const int tid = threadIdx.x;
    const int wid = tid >> 5;
    const int l   = tid & 31;
    const int bj = blockIdx.x, bi = blockIdx.y;

    float* sn1 = (float*)(smem + SM_SN1);
    float* sn2 = (float*)(smem + SM_SN2);
    float* sC  = (float*)(smem + SM_SC);
    unsigned int* srmax = (unsigned int*)(smem + SM_RMAX);
    float* ssum = (float*)(smem + SM_SSUM);

    if (tid < 128) srmax[tid] = 0u;

    // ---- load fp32, split bf16 hi/lo into swizzled smem; fused row reductions ----
    // Each warp covers one full 128-float row per iteration (lane = k/4 chunk),
    // so warp shuffles give exact row reductions. 16 warps -> 8 iterations.
    {
        const float* srcA  = p1 + (size_t)(bi * TILE) * DIM;
        const float* auxA  = p2 + (size_t)(bi * TILE) * DIM;   // for dist_ap
        const float* srcB1 = p1 + (size_t)(bj * TILE) * DIM;
        const float* srcB2 = p2 + (size_t)(bj * TILE) * DIM;

#pragma unroll 1
        for (int it = 0; it < 8; it++) {
            int idx = it * 512 + tid;
            int row = idx >> 5;
            int k = (idx & 31) * 4;
            int woff = row * 128 + (k & 63) * 2;
            int sw = (woff ^ ((woff >> 3) & 0x70)) + ((k >> 6) << 14);

            // A tile (p1 rows of bi) + dist_ap
            float4 a = *(const float4*)(srcA + row * DIM + k);
            float4 b = *(const float4*)(auxA + row * DIM + k);
            BU h0, h1, l0, l1;
            h0.b = __floats2bfloat162_rn(a.x, a.y);
            h1.b = __floats2bfloat162_rn(a.z, a.w);
            l0.b = __floats2bfloat162_rn(a.x - __bfloat162float(h0.b.x),
                                         a.y - __bfloat162float(h0.b.y));
            l1.b = __floats2bfloat162_rn(a.z - __bfloat162float(h1.b.x),
                                         a.w - __bfloat162float(h1.b.y));
            *(uint2*)(smem + SM_OPS + 0 * OP_BYTES + sw) = make_uint2(h0.u, h1.u);
            *(uint2*)(smem + SM_OPS + 1 * OP_BYTES + sw) = make_uint2(l0.u, l1.u);
            float sq = a.x*a.x + a.y*a.y + a.z*a.z + a.w*a.w;
            float dx = a.x-b.x, dy = a.y-b.y, dz = a.z-b.z, dw = a.w-b.w;
            float dq = dx*dx + dy*dy + dz*dz + dw*dw;
#pragma unroll
            for (int m = 16; m; m >>= 1) {
                sq += __shfl_xor_sync(0xffffffffu, sq, m);
                dq += __shfl_xor_sync(0xffffffffu, dq, m);
            }
            if (l == 0) sC[row] = dq - sq + MARGIN;

            // B1 tile (p1 rows of bj)
            a = *(const float4*)(srcB1 + row * DIM + k);
            h0.b = __floats2bfloat162_rn(a.x, a.y);
            h1.b = __floats2bfloat162_rn(a.z, a.w);
            l0.b = __floats2bfloat162_rn(a.x - __bfloat162float(h0.b.x),
                                         a.y - __bfloat162float(h0.b.y));
            l1.b = __floats2bfloat162_rn(a.z - __bfloat162float(h1.b.x),
                                         a.w - __bfloat162float(h1.b.y));
            *(uint2*)(smem + SM_OPS + 2 * OP_BYTES + sw) = make_uint2(h0.u, h1.u);
            *(uint2*)(smem + SM_OPS + 3 * OP_BYTES + sw) = make_uint2(l0.u, l1.u);
            sq = a.x*a.x + a.y*a.y + a.z*a.z + a.w*a.w;
#pragma unroll
            for (int m = 16; m; m >>= 1) sq += __shfl_xor_sync(0xffffffffu, sq, m);
            if (l == 0) sn1[row] = sq;

            // B2 tile (p2 rows of bj)
            a = *(const float4*)(srcB2 + row * DIM + k);
            h0.b = __floats2bfloat162_rn(a.x, a.y);
            h1.b = __floats2bfloat162_rn(a.z, a.w);
            l0.b = __floats2bfloat162_rn(a.x - __bfloat162float(h0.b.x),
                                         a.y - __bfloat162float(h0.b.y));
            l1.b = __floats2bfloat162_rn(a.z - __bfloat162float(h1.b.x),
                                         a.w - __bfloat162float(h1.b.y));
            *(uint2*)(smem + SM_OPS + 4 * OP_BYTES + sw) = make_uint2(h0.u, h1.u);
            *(uint2*)(smem + SM_OPS + 5 * OP_BYTES + sw) = make_uint2(l0.u, l1.u);
            sq = a.x*a.x + a.y*a.y + a.z*a.z + a.w*a.w;
#pragma unroll
            for (int m = 16; m; m >>= 1) sq += __shfl_xor_sync(0xffffffffu, sq, m);
            if (l == 0) sn2[row] = sq;
        }
    }
    __syncthreads();

    // ---- warp tiling: 4 (M) x 4 (N) warps, warp tile 32x32 ----
    const int wm = wid & 3;
    const int wn = wid >> 2;
    const uint32_t AHI = sbase + SM_OPS + 0 * OP_BYTES;
    const uint32_t ALO = sbase + SM_OPS + 1 * OP_BYTES;
    const bool diag = (bi == bj);

    const int qr = l >> 2;            // 0..7 row within frag
    const int qc = (l & 3) * 2;       // col pair base within n8

    float sum = 0.f;

#pragma unroll 1
    for (int pass = 0; pass < 2; pass++) {
        const uint32_t BHI = sbase + SM_OPS + (2 + 2 * pass) * OP_BYTES;
        const uint32_t BLO = BHI + OP_BYTES;

        float acc[2][4][4];
#pragma unroll
        for (int mf = 0; mf < 2; mf++)
#pragma unroll
            for (int nf = 0; nf < 4; nf++)
#pragma unroll
                for (int e = 0; e < 4; e++) acc[mf][nf][e] = 0.f;

        const int arow = wm * 32 + (l & 7) + ((l >> 3) & 1) * 8;
        const int akoff = (l >> 4) * 8;
        const int brow = wn * 32 + (l & 7) + ((l >> 4) << 3);
        const int bkoff = ((l >> 3) & 1) * 8;

#pragma unroll
        for (int ks = 0; ks < 8; ks++) {
            const int k0 = ks * 16;
            uint32_t ah[2][4], al[2][4];
#pragma unroll
            for (int mf = 0; mf < 2; mf++) {
                ldsm4(taddr(AHI, arow + mf * 16, k0 + akoff), ah[mf]);
                ldsm4(taddr(ALO, arow + mf * 16, k0 + akoff), al[mf]);
            }
            uint32_t bh[4][2], bl[4][2];
#pragma unroll
            for (int np = 0; np < 2; np++) {
                uint32_t t[4];
                ldsm4(taddr(BHI, brow + np * 16, k0 + bkoff), t);
                bh[2*np][0] = t[0]; bh[2*np][1] = t[1];
                bh[2*np+1][0] = t[2]; bh[2*np+1][1] = t[3];
                ldsm4(taddr(BLO, brow + np * 16, k0 + bkoff), t);
                bl[2*np][0] = t[0]; bl[2*np][1] = t[1];
                bl[2*np+1][0] = t[2]; bl[2*np+1][1] = t[3];
            }
#pragma unroll
            for (int mf = 0; mf < 2; mf++)
#pragma unroll
                for (int nf = 0; nf < 4; nf++) {
                    MMA(acc[mf][nf], ah[mf], bh[nf]);
                    MMA(acc[mf][nf], ah[mf], bl[nf]);
                    MMA(acc[mf][nf], al[mf], bh[nf]);
                }
        }

        // ---- epilogue for this accumulator ----
        const float* snn = pass ? sn2 : sn1;
        float Cr[2][2], nc[4][2];
#pragma unroll
        for (int mf = 0; mf < 2; mf++) {
            int r0 = wm * 32 + mf * 16 + qr;
            Cr[mf][0] = sC[r0];
            Cr[mf][1] = sC[r0 + 8];
        }
#pragma unroll
        for (int nf = 0; nf < 4; nf++) {
            int c0 = wn * 32 + nf * 8 + qc;
            nc[nf][0] = snn[c0];
            nc[nf][1] = snn[c0 + 1];
        }
        float rmax[2][2];
#pragma unroll
        for (int mf = 0; mf < 2; mf++) { rmax[mf][0] = 0.f; rmax[mf][1] = 0.f; }

#pragma unroll
        for (int mf = 0; mf < 2; mf++)
#pragma unroll
            for (int nf = 0; nf < 4; nf++)
#pragma unroll
                for (int e = 0; e < 4; e++) {
                    int rr = e >> 1, cc = e & 1;
                    float v = fmaxf(Cr[mf][rr] - nc[nf][cc] + 2.f * acc[mf][nf][e], 0.f);
                    if (diag) {
                        int rl = wm * 32 + mf * 16 + qr + rr * 8;
                        int cl = wn * 32 + nf * 8 + qc + cc;
                        if (rl == cl) v = 0.f;
                    }
                    sum += v;
                    rmax[mf][rr] = fmaxf(rmax[mf][rr], v);
                }
        // reduce row-max over the 4 lanes sharing each row
#pragma unroll
        for (int m = 1; m <= 2; m <<= 1)
#pragma unroll
            for (int mf = 0; mf < 2; mf++) {
                rmax[mf][0] = fmaxf(rmax[mf][0], __shfl_xor_sync(0xffffffffu, rmax[mf][0], m));
                rmax[mf][1] = fmaxf(rmax[mf][1], __shfl_xor_sync(0xffffffffu, rmax[mf][1], m));
            }
        if ((l & 3) == 0) {
#pragma unroll
            for (int mf = 0; mf < 2; mf++) {
                atomicMax(&srmax[wm * 32 + mf * 16 + qr],     __float_as_uint(rmax[mf][0]));
                atomicMax(&srmax[wm * 32 + mf * 16 + qr + 8], __float_as_uint(rmax[mf][1]));
            }
        }
    }

    __syncthreads();
    if (tid < 128)
        atomicMax(&g_rowmax[bi * TILE + tid], srmax[tid]);   // vals >= 0: uint order == float order

#pragma unroll
    for (int m = 16; m; m >>= 1) sum += __shfl_xor_sync(0xffffffffu, sum, m);
    if (l == 0) ssum[wid] = sum;
    __syncthreads();
    if (tid == 0) {
        float t = 0.f;
#pragma unroll
        for (int w = 0; w < 16; w++) t += ssum[w];
        g_partial[bi * gridDim.x + bj] = t;
    }
}

// ---- final deterministic reduction (1024 threads, 1 barrier); re-zeros g_rowmax ----
__global__ void __launch_bounds__(1024)
final_kernel(float* __restrict__ out, int n, int nblocks) {
    __shared__ double s1[32];
    __shared__ double s2[32];
    const int tid = threadIdx.x;
    double smax = 0.0, ssumd = 0.0;
#pragma unroll
    for (int r = 0; r < MAXN / 1024; r++) {
        int i = r * 1024 + tid;
        if (i < n) {
            smax += (double)__uint_as_float(g_rowmax[i]);
            g_rowmax[i] = 0u;
        }
    }
    if (tid < nblocks) ssumd += (double)g_partial[tid];
#pragma unroll
    for (int m = 16; m; m >>= 1) {
        smax  += __shfl_xor_sync(0xffffffffu, smax, m);
        ssumd += __shfl_xor_sync(0xffffffffu, ssumd, m);
    }
    if ((tid & 31) == 0) { s1[tid >> 5] = smax; s2[tid >> 5] = ssumd; }
    __syncthreads();
    if (tid == 0) {
        double t1 = 0.0, t2 = 0.0;
#pragma unroll
        for (int w = 0; w < 32; w++) { t1 += s1[w]; t2 += s2[w]; }
        out[0] = (float)(t1 / (double)n);
        out[1] = (float)(t2 / (2.0 * (double)n * (double)(n - 1)));
    }
}

extern "C" void kernel_launch(void* const* d_in, const int* in_sizes, int n_in,
                              void* d_out, int out_size) {
    const float* p1 = (const float*)d_in[0];
    const float* p2 = (const float*)d_in[1];
    float* out = (float*)d_out;
    const int n = in_sizes[0] / DIM;          // 4096
    const int nt = n / TILE;                  // 32

    cudaFuncSetAttribute(triplet_mma_kernel,
                         cudaFuncAttributeMaxDynamicSharedMemorySize, SMEM_TOTAL);

    dim3 grid(nt, nt);
    triplet_mma_kernel<<<grid, 512, SMEM_TOTAL>>>(p1, p2, n);
    final_kernel<<<1, 1024>>>(out, n, nt * nt);
}

// round 5
// speedup vs baseline: 2.3664x; 1.2086x over previous
#include <cuda_runtime.h>
#include <cuda_bf16.h>
#include <cstdint>

#define MARGIN 0.3f
#define DIM  128
#define TILE 128
#define MAXN 4096
#define MAXT (MAXN / TILE)
#define MAXPAIR (MAXT * (MAXT + 1) / 2)

// ---- dynamic smem layout (bytes) ----
#define SM_CBI  0
#define SM_CBJ  512
#define SM_N1BI 1024
#define SM_N1BJ 1536
#define SM_N2BI 2048
#define SM_N2BJ 2560
#define SM_RMI  3072        // 128 uint
#define SM_RMJ  3584        // 128 uint
#define SM_SSUM 4096        // 16 floats
#define SM_OPS  5120        // 1024-aligned
#define CT      16384       // one chunk tile: 128 rows x 64 bf16 cols (SW128)
#define SMEM_TOTAL (SM_OPS + 12 * CT)

// chunk-tile byte offsets within OPS (hi tiles of p1 have chunk0,chunk1 adjacent)
#define T_P1BI_HI 0
#define T_P1BI_LO (2 * CT)
#define T_P1BJ_HI (4 * CT)
#define T_P1BJ_LO (6 * CT)
#define T_P2BJ_HI (8 * CT)      // single-chunk buffers (reloaded per K-phase)
#define T_P2BJ_LO (9 * CT)
#define T_P2BI_HI (10 * CT)
#define T_P2BI_LO (11 * CT)

__device__ float g_n1[MAXN], g_n2[MAXN], g_C[MAXN];
__device__ unsigned int g_rowmax[MAXN];     // zero at load; last CTA re-zeros
__device__ float g_partial[MAXPAIR];
__device__ unsigned int g_ticket;           // zero at load; last CTA re-zeros

__device__ __forceinline__ uint32_t smem_u32(const void* p) {
    uint32_t a;
    asm("{ .reg .u64 t; cvta.to.shared.u64 t, %1; cvt.u32.u64 %0, t; }" : "=r"(a) : "l"(p));
    return a;
}
// swizzled byte offset within one chunk tile (row 0..127, kc 0..63 bf16 cols)
__device__ __forceinline__ int swz(int row, int kc) {
    int b = row * 128 + kc * 2;
    return b ^ ((b >> 3) & 0x70);
}
// address in a 2-chunk (full-K) tile; base0 = smem addr of chunk0 tile
__device__ __forceinline__ uint32_t taddr(uint32_t base0, int row, int kcol) {
    return base0 + ((kcol >> 6) << 14) + swz(row, kcol & 63);
}
__device__ __forceinline__ void ldsm4(uint32_t addr, uint32_t r[4]) {
    asm volatile("ldmatrix.sync.aligned.m8n8.x4.shared.b16 {%0,%1,%2,%3}, [%4];"
                 : "=r"(r[0]), "=r"(r[1]), "=r"(r[2]), "=r"(r[3]) : "r"(addr));
}
#define MMA(d, a, b)                                                               \
    asm volatile("mma.sync.aligned.m16n8k16.row.col.f32.bf16.bf16.f32 "            \
                 "{%0,%1,%2,%3},{%4,%5,%6,%7},{%8,%9},{%0,%1,%2,%3};"              \
                 : "+f"((d)[0]), "+f"((d)[1]), "+f"((d)[2]), "+f"((d)[3])          \
                 : "r"((a)[0]), "r"((a)[1]), "r"((a)[2]), "r"((a)[3]),             \
                   "r"((b)[0]), "r"((b)[1]))

union BU { __nv_bfloat162 b; uint32_t u; };

__device__ __forceinline__ void split_store(char* smem, int dhi, int dlo, float4 a) {
    BU h0, h1, l0, l1;
    h0.b = __floats2bfloat162_rn(a.x, a.y);
    h1.b = __floats2bfloat162_rn(a.z, a.w);
    l0.b = __floats2bfloat162_rn(a.x - __bfloat162float(h0.b.x),
                                 a.y - __bfloat162float(h0.b.y));
    l1.b = __floats2bfloat162_rn(a.z - __bfloat162float(h1.b.x),
                                 a.w - __bfloat162float(h1.b.y));
    *(uint2*)(smem + dhi) = make_uint2(h0.u, h1.u);
    *(uint2*)(smem + dlo) = make_uint2(l0.u, l1.u);
}

// load a/b fragments + 24 MMAs for one kstep into acc[2][4][4]
__device__ __forceinline__ void kstep_mma(
    uint32_t AHI0, uint32_t ALO0, uint32_t BHI0, uint32_t BLO0,
    int k0, int arow, int akoff, int brow, int bkoff, float (&acc)[2][4][4])
{
    uint32_t ah[2][4], al[2][4];
#pragma unroll
    for (int mf = 0; mf < 2; mf++) {
        ldsm4(taddr(AHI0, arow + mf * 16, k0 + akoff), ah[mf]);
        ldsm4(taddr(ALO0, arow + mf * 16, k0 + akoff), al[mf]);
    }
    uint32_t bh[4][2], bl[4][2];
#pragma unroll
    for (int np = 0; np < 2; np++) {
        uint32_t t[4];
        ldsm4(taddr(BHI0, brow + np * 16, k0 + bkoff), t);
        bh[2*np][0] = t[0]; bh[2*np][1] = t[1];
        bh[2*np+1][0] = t[2]; bh[2*np+1][1] = t[3];
        ldsm4(taddr(BLO0, brow + np * 16, k0 + bkoff), t);
        bl[2*np][0] = t[0]; bl[2*np][1] = t[1];
        bl[2*np+1][0] = t[2]; bl[2*np+1][1] = t[3];
    }
#pragma unroll
    for (int mf = 0; mf < 2; mf++)
#pragma unroll
        for (int nf = 0; nf < 4; nf++) {
            MMA(acc[mf][nf], ah[mf], bh[nf]);
            MMA(acc[mf][nf], ah[mf], bl[nf]);
            MMA(acc[mf][nf], al[mf], bh[nf]);
        }
}

// normal-orientation epilogue: rows -> srm (row max), sum accumulation
__device__ __forceinline__ void epi_normal(
    float (&acc)[2][4][4], const float* Crow, const float* ncol,
    int wm, int wn, int qr, int qc, int l, bool dz,
    unsigned int* srm, float& sum)
{
    float Cr[2][2], nc[4][2];
#pragma unroll
    for (int mf = 0; mf < 2; mf++) {
        int r0 = wm * 32 + mf * 16 + qr;
        Cr[mf][0] = Crow[r0]; Cr[mf][1] = Crow[r0 + 8];
    }
#pragma unroll
    for (int nf = 0; nf < 4; nf++) {
        int c0 = wn * 32 + nf * 8 + qc;
        nc[nf][0] = ncol[c0]; nc[nf][1] = ncol[c0 + 1];
    }
    float rmax[2][2] = {{0.f, 0.f}, {0.f, 0.f}};
#pragma unroll
    for (int mf = 0; mf < 2; mf++)
#pragma unroll
        for (int nf = 0; nf < 4; nf++)
#pragma unroll
            for (int e = 0; e < 4; e++) {
                int rr = e >> 1, cc = e & 1;
                float v = fmaxf(Cr[mf][rr] - nc[nf][cc] + 2.f * acc[mf][nf][e], 0.f);
                if (dz) {
                    int rl = wm * 32 + mf * 16 + qr + rr * 8;
                    int cl = wn * 32 + nf * 8 + qc + cc;
                    if (rl == cl) v = 0.f;
                }
                sum += v;
                rmax[mf][rr] = fmaxf(rmax[mf][rr], v);
            }
#pragma unroll
    for (int m = 1; m <= 2; m <<= 1)
#pragma unroll
        for (int mf = 0; mf < 2; mf++) {
            rmax[mf][0] = fmaxf(rmax[mf][0], __shfl_xor_sync(0xffffffffu, rmax[mf][0], m));
            rmax[mf][1] = fmaxf(rmax[mf][1], __shfl_xor_sync(0xffffffffu, rmax[mf][1], m));
        }
    if ((l & 3) == 0) {
#pragma unroll
        for (int mf = 0; mf < 2; mf++) {
            atomicMax(&srm[wm * 32 + mf * 16 + qr],     __float_as_uint(rmax[mf][0]));
            atomicMax(&srm[wm * 32 + mf * 16 + qr + 8], __float_as_uint(rmax[mf][1]));
        }
    }
}

// transposed-orientation epilogue for G1 (off-diag only): cols are anchors
__device__ __forceinline__ void epi_trans(
    float (&acc)[2][4][4], const float* Ccol, const float* nrow,
    int wm, int wn, int qr, int qc, int l,
    unsigned int* srm, float& sum)
{
    float Ct[4][2], nr[2][2];
#pragma unroll
    for (int nf = 0; nf < 4; nf++) {
        int c0 = wn * 32 + nf * 8 + qc;
        Ct[nf][0] = Ccol[c0]; Ct[nf][1] = Ccol[c0 + 1];
    }
#pragma unroll
    for (int mf = 0; mf < 2; mf++) {
        int r0 = wm * 32 + mf * 16 + qr;
        nr[mf][0] = nrow[r0]; nr[mf][1] = nrow[r0 + 8];
    }
    float cmax[4][2] = {{0.f,0.f},{0.f,0.f},{0.f,0.f},{0.f,0.f}};
#pragma unroll
    for (int mf = 0; mf < 2; mf++)
#pragma unroll
        for (int nf = 0; nf < 4; nf++)
#pragma unroll
            for (int e = 0; e < 4; e++) {
                int rr = e >> 1, cc = e & 1;
                float v = fmaxf(Ct[nf][cc] - nr[mf][rr] + 2.f * acc[mf][nf][e], 0.f);
                sum += v;
                cmax[nf][cc] = fmaxf(cmax[nf][cc], v);
            }
#pragma unroll
    for (int m = 4; m <= 16; m <<= 1)
#pragma unroll
        for (int nf = 0; nf < 4; nf++) {
            cmax[nf][0] = fmaxf(cmax[nf][0], __shfl_xor_sync(0xffffffffu, cmax[nf][0], m));
            cmax[nf][1] = fmaxf(cmax[nf][1], __shfl_xor_sync(0xffffffffu, cmax[nf][1], m));
        }
    if (l < 4) {
#pragma unroll
        for (int nf = 0; nf < 4; nf++) {
            int c0 = wn * 32 + nf * 8 + qc;
            atomicMax(&srm[c0],     __float_as_uint(cmax[nf][0]));
            atomicMax(&srm[c0 + 1], __float_as_uint(cmax[nf][1]));
        }
    }
}

// ---- prep: row norms + C per row ----
__global__ void __launch_bounds__(1024)
prep_kernel(const float* __restrict__ p1, const float* __restrict__ p2, int n) {
    int row = blockIdx.x * 32 + (threadIdx.x >> 5);
    int lane = threadIdx.x & 31;
    if (row >= n) return;
    float4 a = ((const float4*)(p1 + (size_t)row * DIM))[lane];
    float4 b = ((const float4*)(p2 + (size_t)row * DIM))[lane];
    float n1 = a.x*a.x + a.y*a.y + a.z*a.z + a.w*a.w;
    float n2 = b.x*b.x + b.y*b.y + b.z*b.z + b.w*b.w;
    float dx = a.x-b.x, dy = a.y-b.y, dz = a.z-b.z, dw = a.w-b.w;
    float dap = dx*dx + dy*dy + dz*dz + dw*dw;
#pragma unroll
    for (int m = 16; m; m >>= 1) {
        n1 += __shfl_xor_sync(0xffffffffu, n1, m);
        n2 += __shfl_xor_sync(0xffffffffu, n2, m);
        dap += __shfl_xor_sync(0xffffffffu, dap, m);
    }
    if (lane == 0) {
        g_n1[row] = n1;
        g_n2[row] = n2;
        g_C[row] = dap - n1 + MARGIN;
    }
}

// ---- main: triangular tiles, dual/normal epilogues, fused finalization ----
__global__ void __launch_bounds__(512)
triplet_tri_kernel(const float* __restrict__ p1, const float* __restrict__ p2,
                   int n, int nt, int npairs) {
    extern __shared__ char smem[];
    const uint32_t sbase = smem_u32(smem);
    const int tid = threadIdx.x;
    const int wid = tid >> 5;
    const int l   = tid & 31;

    // decode triangular pair (bi <= bj)
    int bi = 0, rem = blockIdx.x;
    while (rem >= nt - bi) { rem -= (nt - bi); bi++; }
    const int bj = bi + rem;
    const bool diag = (bi == bj);

    float* sCbi  = (float*)(smem + SM_CBI);
    float* sCbj  = (float*)(smem + SM_CBJ);
    float* sn1bi = (float*)(smem + SM_N1BI);
    float* sn1bj = (float*)(smem + SM_N1BJ);
    float* sn2bi = (float*)(smem + SM_N2BI);
    float* sn2bj = (float*)(smem + SM_N2BJ);
    unsigned int* srm_bi = (unsigned int*)(smem + SM_RMI);
    unsigned int* srm_bj = (unsigned int*)(smem + SM_RMJ);
    float* ssum = (float*)(smem + SM_SSUM);

    if (tid < 128) {
        srm_bi[tid] = 0u; srm_bj[tid] = 0u;
        sCbi[tid]  = g_C[bi * TILE + tid];
        sCbj[tid]  = g_C[bj * TILE + tid];
        sn1bi[tid] = g_n1[bi * TILE + tid];
        sn1bj[tid] = g_n1[bj * TILE + tid];
        sn2bi[tid] = g_n2[bi * TILE + tid];
        sn2bj[tid] = g_n2[bj * TILE + tid];
    }

    // ---- convert phase 0: p1[bi], p1[bj] full-K; p2[bj], p2[bi] chunk 0 ----
#pragma unroll 2
    for (int it = 0; it < 16; it++) {
        int idx = it * 512 + tid;
        int t = idx >> 12;                 // 0: p1bi, 1: p1bj
        int r = (idx >> 5) & 127;
        int kc = (idx & 31) * 4;
        const float* src = p1 + (size_t)((t ? bj : bi) * TILE + r) * DIM + kc;
        float4 a = *(const float4*)src;
        int off = ((kc >> 6) << 14) + swz(r, kc & 63);
        int hib = SM_OPS + (t ? T_P1BJ_HI : T_P1BI_HI) + off;
        int lob = SM_OPS + (t ? T_P1BJ_LO : T_P1BI_LO) + off;
        split_store(smem, hib, lob, a);
    }
#pragma unroll 2
    for (int it = 0; it < 8; it++) {
        int idx = it * 512 + tid;
        int t = idx >> 11;                 // 0: p2bj, 1: p2bi
        int r = (idx >> 4) & 127;
        int kcl = (idx & 15) * 4;          // within-chunk col
        const float* src = p2 + (size_t)((t ? bi : bj) * TILE + r) * DIM + kcl; // chunk 0
        float4 a = *(const float4*)src;
        int off = swz(r, kcl);
        int hib = SM_OPS + (t ? T_P2BI_HI : T_P2BJ_HI) + off;
        int lob = SM_OPS + (t ? T_P2BI_LO : T_P2BJ_LO) + off;
        split_store(smem, hib, lob, a);
    }
    __syncthreads();

    // warp tiling 4x4, warp tile 32x32
    const int wm = wid & 3;
    const int wn = wid >> 2;
    const int qr = l >> 2;
    const int qc = (l & 3) * 2;
    const int arow = wm * 32 + (l & 7) + ((l >> 3) & 1) * 8;
    const int akoff = (l >> 4) * 8;
    const int brow = wn * 32 + (l & 7) + ((l >> 4) << 3);
    const int bkoff = ((l >> 3) & 1) * 8;

    float sum = 0.f;

    // ---- G1 = p1[bi] . p1[bj]^T : full K (8 ksteps) ----
    {
        float acc[2][4][4];
#pragma unroll
        for (int mf = 0; mf < 2; mf++)
#pragma unroll
            for (int nf = 0; nf < 4; nf++)
#pragma unroll
                for (int e = 0; e < 4; e++) acc[mf][nf][e] = 0.f;
#pragma unroll
        for (int ks = 0; ks < 8; ks++)
            kstep_mma(sbase + SM_OPS + T_P1BI_HI, sbase + SM_OPS + T_P1BI_LO,
                      sbase + SM_OPS + T_P1BJ_HI, sbase + SM_OPS + T_P1BJ_LO,
                      ks * 16, arow, akoff, brow, bkoff, acc);
        epi_normal(acc, sCbi, sn1bj, wm, wn, qr, qc, l, diag, srm_bi, sum);
        if (!diag)
            epi_trans(acc, sCbj, sn1bi, wm, wn, qr, qc, l, srm_bj, sum);
    }

    // ---- G2a = p1[bi] . p2[bj]^T ; G2b = p1[bj] . p2[bi]^T : chunked K ----
    {
        float acc2a[2][4][4], acc2b[2][4][4];
#pragma unroll
        for (int mf = 0; mf < 2; mf++)
#pragma unroll
            for (int nf = 0; nf < 4; nf++)
#pragma unroll
                for (int e = 0; e < 4; e++) { acc2a[mf][nf][e] = 0.f; acc2b[mf][nf][e] = 0.f; }

#pragma unroll 1
        for (int ph = 0; ph < 2; ph++) {
            if (ph == 1) {
                __syncthreads();   // chunk-0 reads done
#pragma unroll 2
                for (int it = 0; it < 8; it++) {
                    int idx = it * 512 + tid;
                    int t = idx >> 11;
                    int r = (idx >> 4) & 127;
                    int kcl = (idx & 15) * 4;
                    const float* src = p2 + (size_t)((t ? bi : bj) * TILE + r) * DIM + 64 + kcl;
                    float4 a = *(const float4*)src;
                    int off = swz(r, kcl);
                    int hib = SM_OPS + (t ? T_P2BI_HI : T_P2BJ_HI) + off;
                    int lob = SM_OPS + (t ? T_P2BI_LO : T_P2BJ_LO) + off;
                    split_store(smem, hib, lob, a);
                }
                __syncthreads();
            }
#pragma unroll
            for (int ks = 0; ks < 4; ks++) {
                int kg = ph * 64 + ks * 16;   // global k for A tiles
                int kl = ks * 16;             // local k for B chunk buffers
                // G2a: A = p1bi, B = p2bj
                {
                    uint32_t ah[2][4], al[2][4];
#pragma unroll
                    for (int mf = 0; mf < 2; mf++) {
                        ldsm4(taddr(sbase + SM_OPS + T_P1BI_HI, arow + mf*16, kg + akoff), ah[mf]);
                        ldsm4(taddr(sbase + SM_OPS + T_P1BI_LO, arow + mf*16, kg + akoff), al[mf]);
                    }
                    uint32_t bh[4][2], bl[4][2];
#pragma unroll
                    for (int np = 0; np < 2; np++) {
                        uint32_t t4[4];
                        ldsm4(sbase + SM_OPS + T_P2BJ_HI + swz(brow + np*16, kl + bkoff), t4);
                        bh[2*np][0]=t4[0]; bh[2*np][1]=t4[1]; bh[2*np+1][0]=t4[2]; bh[2*np+1][1]=t4[3];
                        ldsm4(sbase + SM_OPS + T_P2BJ_LO + swz(brow + np*16, kl + bkoff), t4);
                        bl[2*np][0]=t4[0]; bl[2*np][1]=t4[1]; bl[2*np+1][0]=t4[2]; bl[2*np+1][1]=t4[3];
                    }
#pragma unroll
                    for (int mf = 0; mf < 2; mf++)
#pragma unroll
                        for (int nf = 0; nf < 4; nf++) {
                            MMA(acc2a[mf][nf], ah[mf], bh[nf]);
                            MMA(acc2a[mf][nf], ah[mf], bl[nf]);
                            MMA(acc2a[mf][nf], al[mf], bh[nf]);
                        }
                }
                // G2b: A = p1bj, B = p2bi (skip on diagonal)
                if (!diag) {
                    uint32_t ah[2][4], al[2][4];
#pragma unroll
                    for (int mf = 0; mf < 2; mf++) {
                        ldsm4(taddr(sbase + SM_OPS + T_P1BJ_HI, arow + mf*16, kg + akoff), ah[mf]);
                        ldsm4(taddr(sbase + SM_OPS + T_P1BJ_LO, arow + mf*16, kg + akoff), al[mf]);
                    }
                    uint32_t bh[4][2], bl[4][2];
#pragma unroll
                    for (int np = 0; np < 2; np++) {
                        uint32_t t4[4];
                        ldsm4(sbase + SM_OPS + T_P2BI_HI + swz(brow + np*16, kl + bkoff), t4);
                        bh[2*np][0]=t4[0]; bh[2*np][1]=t4[1]; bh[2*np+1][0]=t4[2]; bh[2*np+1][1]=t4[3];
                        ldsm4(sbase + SM_OPS + T_P2BI_LO + swz(brow + np*16, kl + bkoff), t4);
                        bl[2*np][0]=t4[0]; bl[2*np][1]=t4[1]; bl[2*np+1][0]=t4[2]; bl[2*np+1][1]=t4[3];
                    }
#pragma unroll
                    for (int mf = 0; mf < 2; mf++)
#pragma unroll
                        for (int nf = 0; nf < 4; nf++) {
                            MMA(acc2b[mf][nf], ah[mf], bh[nf]);
                            MMA(acc2b[mf][nf], ah[mf], bl[nf]);
                            MMA(acc2b[mf][nf], al[mf], bh[nf]);
                        }
                }
            }
        }
        // L2 tile (bi,bj): rows bi anchors, diag-zero if bi==bj
        epi_normal(acc2a, sCbi, sn2bj, wm, wn, qr, qc, l, diag, srm_bi, sum);
        // L2 tile (bj,bi): rows bj anchors (off-diag only)
        if (!diag)
            epi_normal(acc2b, sCbj, sn2bi, wm, wn, qr, qc, l, false, srm_bj, sum);
    }

    // ---- block reduction + global publish ----
#pragma unroll
    for (int m = 16; m; m >>= 1) sum += __shfl_xor_sync(0xffffffffu, sum, m);
    if (l == 0) ssum[wid] = sum;
    __syncthreads();

    if (tid < 128)
        atomicMax(&g_rowmax[bi * TILE + tid], srm_bi[tid]);
    else if (tid < 256 && !diag)
        atomicMax(&g_rowmax[bj * TILE + (tid - 128)], srm_bj[tid - 128]);
    if (tid == 0) {
        float t = 0.f;
#pragma unroll
        for (int w = 0; w < 16; w++) t += ssum[w];
        g_partial[blockIdx.x] = t;
    }
    __threadfence();
    __syncthreads();

    // ---- last-CTA fused finalization ----
    __shared__ unsigned int s_last;
    if (tid == 0) s_last = (atomicAdd(&g_ticket, 1u) == (unsigned)(npairs - 1));
    __syncthreads();
    if (!s_last) return;
    __threadfence();

    double smax = 0.0, ssumd = 0.0;
    for (int i = tid; i < n; i += 512) {
        smax += (double)__uint_as_float(g_rowmax[i]);
        g_rowmax[i] = 0u;                       // reset for next replay
    }
    for (int i = tid; i < npairs; i += 512) ssumd += (double)g_partial[i];
#pragma unroll
    for (int m = 16; m; m >>= 1) {
        smax  += __shfl_xor_sync(0xffffffffu, smax, m);
        ssumd += __shfl_xor_sync(0xffffffffu, ssumd, m);
    }
    __shared__ double d1[16], d2[16];
    if (l == 0) { d1[wid] = smax; d2[wid] = ssumd; }
    __syncthreads();
    if (tid == 0) {
        double t1 = 0.0, t2 = 0.0;
#pragma unroll
        for (int w = 0; w < 16; w++) { t1 += d1[w]; t2 += d2[w]; }
        float* out = (float*)(((char**)0)[0]);  // placeholder never used
        (void)out;
        g_ticket = 0;                           // reset for next replay
        // results stashed in g_partial[0..1]? No: write directly via param below.
        d1[0] = t1; d2[0] = t2;
    }
    __syncthreads();
    if (tid == 0) {
        // write outputs (passed via constant param)
        extern __device__ float* g_outp;        // resolved below
    }
}

// NOTE: output pointer plumbing — we pass `out` as a kernel parameter instead.
// The block above is unreachable dead code guarded rewrite; see kernel below.

__global__ void __launch_bounds__(512)
dummy_unused() {}

// Rewritten driver: pass out pointer into the main kernel.
__global__ void __launch_bounds__(512)
triplet_tri_kernel2(const float* __restrict__ p1, const float* __restrict__ p2,
                    float* __restrict__ out, int n, int nt, int npairs);

extern "C" void kernel_launch(void* const* d_in, const int* in_sizes, int n_in,
                              void* d_out, int out_size) {
    const float* p1 = (const float*)d_in[0];
    const float* p2 = (const float*)d_in[1];
    float* out = (float*)d_out;
    const int n = in_sizes[0] / DIM;            // 4096
    const int nt = n / TILE;                    // 32
    const int npairs = nt * (nt + 1) / 2;       // 528

    cudaFuncSetAttribute(triplet_tri_kernel2,
                         cudaFuncAttributeMaxDynamicSharedMemorySize, SMEM_TOTAL);

    prep_kernel<<<n / 32, 1024>>>(p1, p2, n);
    triplet_tri_kernel2<<<npairs, 512, SMEM_TOTAL>>>(p1, p2, out, n, nt, npairs);
}

// ---- the real main kernel (same as above, with out param and clean tail) ----
__global__ void __launch_bounds__(512)
triplet_tri_kernel2(const float* __restrict__ p1, const float* __restrict__ p2,
                    float* __restrict__ out, int n, int nt, int npairs) {
    extern __shared__ char smem[];
    const uint32_t sbase = smem_u32(smem);
    const int tid = threadIdx.x;
    const int wid = tid >> 5;
    const int l   = tid & 31;

    int bi = 0, rem = blockIdx.x;
    while (rem >= nt - bi) { rem -= (nt - bi); bi++; }
    const int bj = bi + rem;
    const bool diag = (bi == bj);

    float* sCbi  = (float*)(smem + SM_CBI);
    float* sCbj  = (float*)(smem + SM_CBJ);
    float* sn1bi = (float*)(smem + SM_N1BI);
    float* sn1bj = (float*)(smem + SM_N1BJ);
    float* sn2bi = (float*)(smem + SM_N2BI);
    float* sn2bj = (float*)(smem + SM_N2BJ);
    unsigned int* srm_bi = (unsigned int*)(smem + SM_RMI);
    unsigned int* srm_bj = (unsigned int*)(smem + SM_RMJ);
    float* ssum = (float*)(smem + SM_SSUM);

    if (tid < 128) {
        srm_bi[tid] = 0u; srm_bj[tid] = 0u;
        sCbi[tid]  = g_C[bi * TILE + tid];
        sCbj[tid]  = g_C[bj * TILE + tid];
        sn1bi[tid] = g_n1[bi * TILE + tid];
        sn1bj[tid] = g_n1[bj * TILE + tid];
        sn2bi[tid] = g_n2[bi * TILE + tid];
        sn2bj[tid] = g_n2[bj * TILE + tid];
    }

#pragma unroll 2
    for (int it = 0; it < 16; it++) {
        int idx = it * 512 + tid;
        int t = idx >> 12;
        int r = (idx >> 5) & 127;
        int kc = (idx & 31) * 4;
        float4 a = *(const float4*)(p1 + (size_t)((t ? bj : bi) * TILE + r) * DIM + kc);
        int off = ((kc >> 6) << 14) + swz(r, kc & 63);
        split_store(smem, SM_OPS + (t ? T_P1BJ_HI : T_P1BI_HI) + off,
                          SM_OPS + (t ? T_P1BJ_LO : T_P1BI_LO) + off, a);
    }
#pragma unroll 2
    for (int it = 0; it < 8; it++) {
        int idx = it * 512 + tid;
        int t = idx >> 11;
        int r = (idx >> 4) & 127;
        int kcl = (idx & 15) * 4;
        float4 a = *(const float4*)(p2 + (size_t)((t ? bi : bj) * TILE + r) * DIM + kcl);
        int off = swz(r, kcl);
        split_store(smem, SM_OPS + (t ? T_P2BI_HI : T_P2BJ_HI) + off,
                          SM_OPS + (t ? T_P2BI_LO : T_P2BJ_LO) + off, a);
    }
    __syncthreads();

    const int wm = wid & 3;
    const int wn = wid >> 2;
    const int qr = l >> 2;
    const int qc = (l & 3) * 2;
    const int arow = wm * 32 + (l & 7) + ((l >> 3) & 1) * 8;
    const int akoff = (l >> 4) * 8;
    const int brow = wn * 32 + (l & 7) + ((l >> 4) << 3);
    const int bkoff = ((l >> 3) & 1) * 8;

    float sum = 0.f;

    {
        float acc[2][4][4];
#pragma unroll
        for (int mf = 0; mf < 2; mf++)
#pragma unroll
            for (int nf = 0; nf < 4; nf++)
#pragma unroll
                for (int e = 0; e < 4; e++) acc[mf][nf][e] = 0.f;
#pragma unroll
        for (int ks = 0; ks < 8; ks++)
            kstep_mma(sbase + SM_OPS + T_P1BI_HI, sbase + SM_OPS + T_P1BI_LO,
                      sbase + SM_OPS + T_P1BJ_HI, sbase + SM_OPS + T_P1BJ_LO,
                      ks * 16, arow, akoff, brow, bkoff, acc);
        epi_normal(acc, sCbi, sn1bj, wm, wn, qr, qc, l, diag, srm_bi, sum);
        if (!diag)
            epi_trans(acc, sCbj, sn1bi, wm, wn, qr, qc, l, srm_bj, sum);
    }

    {
        float acc2a[2][4][4], acc2b[2][4][4];
#pragma unroll
        for (int mf = 0; mf < 2; mf++)
#pragma unroll
            for (int nf = 0; nf < 4; nf++)
#pragma unroll
                for (int e = 0; e < 4; e++) { acc2a[mf][nf][e] = 0.f; acc2b[mf][nf][e] = 0.f; }

#pragma unroll 1
        for (int ph = 0; ph < 2; ph++) {
            if (ph == 1) {
                __syncthreads();
#pragma unroll 2
                for (int it = 0; it < 8; it++) {
                    int idx = it * 512 + tid;
                    int t = idx >> 11;
                    int r = (idx >> 4) & 127;
                    int kcl = (idx & 15) * 4;
                    float4 a = *(const float4*)(p2 + (size_t)((t ? bi : bj) * TILE + r) * DIM + 64 + kcl);
                    int off = swz(r, kcl);
                    split_store(smem, SM_OPS + (t ? T_P2BI_HI : T_P2BJ_HI) + off,
                                      SM_OPS + (t ? T_P2BI_LO : T_P2BJ_LO) + off, a);
                }
                __syncthreads();
            }
#pragma unroll
            for (int ks = 0; ks < 4; ks++) {
                int kg = ph * 64 + ks * 16;
                int kl = ks * 16;
                {
                    uint32_t ah[2][4], al[2][4];
#pragma unroll
                    for (int mf = 0; mf < 2; mf++) {
                        ldsm4(taddr(sbase + SM_OPS + T_P1BI_HI, arow + mf*16, kg + akoff), ah[mf]);
                        ldsm4(taddr(sbase + SM_OPS + T_P1BI_LO, arow + mf*16, kg + akoff), al[mf]);
                    }
                    uint32_t bh[4][2], bl[4][2];
#pragma unroll
                    for (int np = 0; np < 2; np++) {
                        uint32_t t4[4];
                        ldsm4(sbase + SM_OPS + T_P2BJ_HI + swz(brow + np*16, kl + bkoff), t4);
                        bh[2*np][0]=t4[0]; bh[2*np][1]=t4[1]; bh[2*np+1][0]=t4[2]; bh[2*np+1][1]=t4[3];
                        ldsm4(sbase + SM_OPS + T_P2BJ_LO + swz(brow + np*16, kl + bkoff), t4);
                        bl[2*np][0]=t4[0]; bl[2*np][1]=t4[1]; bl[2*np+1][0]=t4[2]; bl[2*np+1][1]=t4[3];
                    }
#pragma unroll
                    for (int mf = 0; mf < 2; mf++)
#pragma unroll
                        for (int nf = 0; nf < 4; nf++) {
                            MMA(acc2a[mf][nf], ah[mf], bh[nf]);
                            MMA(acc2a[mf][nf], ah[mf], bl[nf]);
                            MMA(acc2a[mf][nf], al[mf], bh[nf]);
                        }
                }
                if (!diag) {
                    uint32_t ah[2][4], al[2][4];
#pragma unroll
                    for (int mf = 0; mf < 2; mf++) {
                        ldsm4(taddr(sbase + SM_OPS + T_P1BJ_HI, arow + mf*16, kg + akoff), ah[mf]);
                        ldsm4(taddr(sbase + SM_OPS + T_P1BJ_LO, arow + mf*16, kg + akoff), al[mf]);
                    }
                    uint32_t bh[4][2], bl[4][2];
#pragma unroll
                    for (int np = 0; np < 2; np++) {
                        uint32_t t4[4];
                        ldsm4(sbase + SM_OPS + T_P2BI_HI + swz(brow + np*16, kl + bkoff), t4);
                        bh[2*np][0]=t4[0]; bh[2*np][1]=t4[1]; bh[2*np+1][0]=t4[2]; bh[2*np+1][1]=t4[3];
                        ldsm4(sbase + SM_OPS + T_P2BI_LO + swz(brow + np*16, kl + bkoff), t4);
                        bl[2*np][0]=t4[0]; bl[2*np][1]=t4[1]; bl[2*np+1][0]=t4[2]; bl[2*np+1][1]=t4[3];
                    }
#pragma unroll
                    for (int mf = 0; mf < 2; mf++)
#pragma unroll
                        for (int nf = 0; nf < 4; nf++) {
                            MMA(acc2b[mf][nf], ah[mf], bh[nf]);
                            MMA(acc2b[mf][nf], ah[mf], bl[nf]);
                            MMA(acc2b[mf][nf], al[mf], bh[nf]);
                        }
                }
            }
        }
        epi_normal(acc2a, sCbi, sn2bj, wm, wn, qr, qc, l, diag, srm_bi, sum);
        if (!diag)
            epi_normal(acc2b, sCbj, sn2bi, wm, wn, qr, qc, l, false, srm_bj, sum);
    }

#pragma unroll
    for (int m = 16; m; m >>= 1) sum += __shfl_xor_sync(0xffffffffu, sum, m);
    if (l == 0) ssum[wid] = sum;
    __syncthreads();

    if (tid < 128)
        atomicMax(&g_rowmax[bi * TILE + tid], srm_bi[tid]);
    else if (tid < 256 && !diag)
        atomicMax(&g_rowmax[bj * TILE + (tid - 128)], srm_bj[tid - 128]);
    if (tid == 0) {
        float t = 0.f;
#pragma unroll
        for (int w = 0; w < 16; w++) t += ssum[w];
        g_partial[blockIdx.x] = t;
    }
    __threadfence();
    __syncthreads();

    __shared__ unsigned int s_last;
    if (tid == 0) s_last = (atomicAdd(&g_ticket, 1u) == (unsigned)(npairs - 1)) ? 1u : 0u;
    __syncthreads();
    if (!s_last) return;
    __threadfence();

    double smax = 0.0, ssumd = 0.0;
    for (int i = tid; i < n; i += 512) {
        smax += (double)__uint_as_float(g_rowmax[i]);
        g_rowmax[i] = 0u;
    }
    for (int i = tid; i < npairs; i += 512) ssumd += (double)g_partial[i];
#pragma unroll
    for (int m = 16; m; m >>= 1) {
        smax  += __shfl_xor_sync(0xffffffffu, smax, m);
        ssumd += __shfl_xor_sync(0xffffffffu, ssumd, m);
    }
    __shared__ double d1[16], d2[16];
    if (l == 0) { d1[wid] = smax; d2[wid] = ssumd; }
    __syncthreads();
    if (tid == 0) {
        double t1 = 0.0, t2 = 0.0;
#pragma unroll
        for (int w = 0; w < 16; w++) { t1 += d1[w]; t2 += d2[w]; }
        out[0] = (float)(t1 / (double)n);
        out[1] = (float)(t2 / (2.0 * (double)n * (double)(n - 1)));
        g_ticket = 0;
    }
}

// round 6
// speedup vs baseline: 2.3760x; 1.0041x over previous
#include <cuda_runtime.h>
#include <cuda_bf16.h>
#include <cstdint>

#define MARGIN 0.3f
#define DIM  128
#define TILE 128
#define MAXN 4096
#define MAXT (MAXN / TILE)
#define MAXPAIR (MAXT * (MAXT + 1) / 2)
#define CT   16384                 // one chunk tile: 128 rows x 64 bf16 cols (SW128)

// ---- dynamic smem layout (bytes) ----
#define SM_CBI  0
#define SM_CBJ  512
#define SM_N1BI 1024
#define SM_N1BJ 1536
#define SM_N2BI 2048
#define SM_N2BJ 2560
#define SM_RMI  3072        // 128 uint
#define SM_RMJ  3584        // 128 uint
#define SM_SSUM 4096        // 16 floats
#define SM_OPS  5120        // 1024-aligned operand region: 12 x 16KB
#define SMEM_TOTAL (SM_OPS + 12 * CT)

// operand offsets within OPS (each op: hi chunk0, hi chunk1, lo chunk0, lo chunk1)
#define T_P1BI_HI 0
#define T_P1BI_LO (2 * CT)
#define T_P1BJ_HI (4 * CT)
#define T_P1BJ_LO (6 * CT)
#define T_P2_HI   (8 * CT)        // holds p2[bj] first, reloaded with p2[bi] for G2b
#define T_P2_LO   (10 * CT)

__device__ float g_n1[MAXN], g_n2[MAXN], g_C[MAXN];
__device__ unsigned int g_rowmax[MAXN];     // zero at load; last CTA re-zeros
__device__ float g_partial[MAXPAIR];
__device__ unsigned int g_ticket;           // zero at load; last CTA re-zeros

// pre-swizzled bf16 hi/lo smem images: [tile][chunk][16KB]
__device__ __align__(16) unsigned char g_img_p1h[MAXT * 2 * CT];
__device__ __align__(16) unsigned char g_img_p1l[MAXT * 2 * CT];
__device__ __align__(16) unsigned char g_img_p2h[MAXT * 2 * CT];
__device__ __align__(16) unsigned char g_img_p2l[MAXT * 2 * CT];

__device__ __forceinline__ uint32_t smem_u32(const void* p) {
    uint32_t a;
    asm("{ .reg .u64 t; cvta.to.shared.u64 t, %1; cvt.u32.u64 %0, t; }" : "=r"(a) : "l"(p));
    return a;
}
__device__ __forceinline__ int swz(int row, int kc) {   // within one chunk tile
    int b = row * 128 + kc * 2;
    return b ^ ((b >> 3) & 0x70);
}
__device__ __forceinline__ uint32_t taddr(uint32_t base0, int row, int kcol) {
    return base0 + ((kcol >> 6) << 14) + swz(row, kcol & 63);
}
__device__ __forceinline__ void ldsm4(uint32_t addr, uint32_t r[4]) {
    asm volatile("ldmatrix.sync.aligned.m8n8.x4.shared.b16 {%0,%1,%2,%3}, [%4];"
                 : "=r"(r[0]), "=r"(r[1]), "=r"(r[2]), "=r"(r[3]) : "r"(addr));
}
__device__ __forceinline__ void cp16(uint32_t saddr, const void* g) {
    asm volatile("cp.async.cg.shared.global [%0], [%1], 16;" :: "r"(saddr), "l"(g));
}
#define CP_COMMIT() asm volatile("cp.async.commit_group;" ::: "memory")
#define CP_WAIT0()  asm volatile("cp.async.wait_group 0;" ::: "memory")

#define MMA(d, a, b)                                                               \
    asm volatile("mma.sync.aligned.m16n8k16.row.col.f32.bf16.bf16.f32 "            \
                 "{%0,%1,%2,%3},{%4,%5,%6,%7},{%8,%9},{%0,%1,%2,%3};"              \
                 : "+f"((d)[0]), "+f"((d)[1]), "+f"((d)[2]), "+f"((d)[3])          \
                 : "r"((a)[0]), "r"((a)[1]), "r"((a)[2]), "r"((a)[3]),             \
                   "r"((b)[0]), "r"((b)[1]))

union BU { __nv_bfloat162 b; uint32_t u; };

// G2b-style single-gram kstep: 8 ldsm, 24 MMAs
__device__ __forceinline__ void kstep_mma(
    uint32_t AHI0, uint32_t ALO0, uint32_t BHI0, uint32_t BLO0,
    int k0, int arow, int akoff, int brow, int bkoff, float (&acc)[2][4][4])
{
    uint32_t ah[2][4], al[2][4];
#pragma unroll
    for (int mf = 0; mf < 2; mf++) {
        ldsm4(taddr(AHI0, arow + mf * 16, k0 + akoff), ah[mf]);
        ldsm4(taddr(ALO0, arow + mf * 16, k0 + akoff), al[mf]);
    }
    uint32_t bh[4][2], bl[4][2];
#pragma unroll
    for (int np = 0; np < 2; np++) {
        uint32_t t[4];
        ldsm4(taddr(BHI0, brow + np * 16, k0 + bkoff), t);
        bh[2*np][0] = t[0]; bh[2*np][1] = t[1];
        bh[2*np+1][0] = t[2]; bh[2*np+1][1] = t[3];
        ldsm4(taddr(BLO0, brow + np * 16, k0 + bkoff), t);
        bl[2*np][0] = t[0]; bl[2*np][1] = t[1];
        bl[2*np+1][0] = t[2]; bl[2*np+1][1] = t[3];
    }
#pragma unroll
    for (int mf = 0; mf < 2; mf++)
#pragma unroll
        for (int nf = 0; nf < 4; nf++) {
            MMA(acc[mf][nf], ah[mf], bh[nf]);
            MMA(acc[mf][nf], ah[mf], bl[nf]);
            MMA(acc[mf][nf], al[mf], bh[nf]);
        }
}

__device__ __forceinline__ void epi_normal(
    float (&acc)[2][4][4], const float* Crow, const float* ncol,
    int wm, int wn, int qr, int qc, int l, bool dz,
    unsigned int* srm, float& sum)
{
    float Cr[2][2], nc[4][2];
#pragma unroll
    for (int mf = 0; mf < 2; mf++) {
        int r0 = wm * 32 + mf * 16 + qr;
        Cr[mf][0] = Crow[r0]; Cr[mf][1] = Crow[r0 + 8];
    }
#pragma unroll
    for (int nf = 0; nf < 4; nf++) {
        int c0 = wn * 32 + nf * 8 + qc;
        nc[nf][0] = ncol[c0]; nc[nf][1] = ncol[c0 + 1];
    }
    float rmax[2][2] = {{0.f, 0.f}, {0.f, 0.f}};
#pragma unroll
    for (int mf = 0; mf < 2; mf++)
#pragma unroll
        for (int nf = 0; nf < 4; nf++)
#pragma unroll
            for (int e = 0; e < 4; e++) {
                int rr = e >> 1, cc = e & 1;
                float v = fmaxf(Cr[mf][rr] - nc[nf][cc] + 2.f * acc[mf][nf][e], 0.f);
                if (dz) {
                    int rl = wm * 32 + mf * 16 + qr + rr * 8;
                    int cl = wn * 32 + nf * 8 + qc + cc;
                    if (rl == cl) v = 0.f;
                }
                sum += v;
                rmax[mf][rr] = fmaxf(rmax[mf][rr], v);
            }
#pragma unroll
    for (int m = 1; m <= 2; m <<= 1)
#pragma unroll
        for (int mf = 0; mf < 2; mf++) {
            rmax[mf][0] = fmaxf(rmax[mf][0], __shfl_xor_sync(0xffffffffu, rmax[mf][0], m));
            rmax[mf][1] = fmaxf(rmax[mf][1], __shfl_xor_sync(0xffffffffu, rmax[mf][1], m));
        }
    if ((l & 3) == 0) {
#pragma unroll
        for (int mf = 0; mf < 2; mf++) {
            atomicMax(&srm[wm * 32 + mf * 16 + qr],     __float_as_uint(rmax[mf][0]));
            atomicMax(&srm[wm * 32 + mf * 16 + qr + 8], __float_as_uint(rmax[mf][1]));
        }
    }
}

__device__ __forceinline__ void epi_trans(
    float (&acc)[2][4][4], const float* Ccol, const float* nrow,
    int wm, int wn, int qr, int qc, int l,
    unsigned int* srm, float& sum)
{
    float Ct[4][2], nr[2][2];
#pragma unroll
    for (int nf = 0; nf < 4; nf++) {
        int c0 = wn * 32 + nf * 8 + qc;
        Ct[nf][0] = Ccol[c0]; Ct[nf][1] = Ccol[c0 + 1];
    }
#pragma unroll
    for (int mf = 0; mf < 2; mf++) {
        int r0 = wm * 32 + mf * 16 + qr;
        nr[mf][0] = nrow[r0]; nr[mf][1] = nrow[r0 + 8];
    }
    float cmax[4][2] = {{0.f,0.f},{0.f,0.f},{0.f,0.f},{0.f,0.f}};
#pragma unroll
    for (int mf = 0; mf < 2; mf++)
#pragma unroll
        for (int nf = 0; nf < 4; nf++)
#pragma unroll
            for (int e = 0; e < 4; e++) {
                int rr = e >> 1, cc = e & 1;
                float v = fmaxf(Ct[nf][cc] - nr[mf][rr] + 2.f * acc[mf][nf][e], 0.f);
                sum += v;
                cmax[nf][cc] = fmaxf(cmax[nf][cc], v);
            }
#pragma unroll
    for (int m = 4; m <= 16; m <<= 1)
#pragma unroll
        for (int nf = 0; nf < 4; nf++) {
            cmax[nf][0] = fmaxf(cmax[nf][0], __shfl_xor_sync(0xffffffffu, cmax[nf][0], m));
            cmax[nf][1] = fmaxf(cmax[nf][1], __shfl_xor_sync(0xffffffffu, cmax[nf][1], m));
        }
    if (l < 4) {
#pragma unroll
        for (int nf = 0; nf < 4; nf++) {
            int c0 = wn * 32 + nf * 8 + qc;
            atomicMax(&srm[c0],     __float_as_uint(cmax[nf][0]));
            atomicMax(&srm[c0 + 1], __float_as_uint(cmax[nf][1]));
        }
    }
}

// ---- prep: norms/C + pre-swizzled bf16 hi/lo images of p1, p2 ----
__global__ void __launch_bounds__(1024)
prep_kernel(const float* __restrict__ p1, const float* __restrict__ p2, int n) {
    int row = blockIdx.x * 32 + (threadIdx.x >> 5);
    int lane = threadIdx.x & 31;
    if (row >= n) return;
    float4 a = ((const float4*)(p1 + (size_t)row * DIM))[lane];
    float4 b = ((const float4*)(p2 + (size_t)row * DIM))[lane];

    float n1 = a.x*a.x + a.y*a.y + a.z*a.z + a.w*a.w;
    float n2 = b.x*b.x + b.y*b.y + b.z*b.z + b.w*b.w;
    float dx = a.x-b.x, dy = a.y-b.y, dz = a.z-b.z, dw = a.w-b.w;
    float dap = dx*dx + dy*dy + dz*dz + dw*dw;
#pragma unroll
    for (int m = 16; m; m >>= 1) {
        n1 += __shfl_xor_sync(0xffffffffu, n1, m);
        n2 += __shfl_xor_sync(0xffffffffu, n2, m);
        dap += __shfl_xor_sync(0xffffffffu, dap, m);
    }
    if (lane == 0) {
        g_n1[row] = n1; g_n2[row] = n2; g_C[row] = dap - n1 + MARGIN;
    }

    int tile = row >> 7, lr = row & 127;
    int c4 = lane * 4, chunk = c4 >> 6, lc = c4 & 63;
    size_t off = (size_t)(tile * 2 + chunk) * CT + swz(lr, lc);

    BU h0, h1, l0, l1;
    h0.b = __floats2bfloat162_rn(a.x, a.y);
    h1.b = __floats2bfloat162_rn(a.z, a.w);
    l0.b = __floats2bfloat162_rn(a.x - __bfloat162float(h0.b.x), a.y - __bfloat162float(h0.b.y));
    l1.b = __floats2bfloat162_rn(a.z - __bfloat162float(h1.b.x), a.w - __bfloat162float(h1.b.y));
    *(uint2*)(g_img_p1h + off) = make_uint2(h0.u, h1.u);
    *(uint2*)(g_img_p1l + off) = make_uint2(l0.u, l1.u);

    h0.b = __floats2bfloat162_rn(b.x, b.y);
    h1.b = __floats2bfloat162_rn(b.z, b.w);
    l0.b = __floats2bfloat162_rn(b.x - __bfloat162float(h0.b.x), b.y - __bfloat162float(h0.b.y));
    l1.b = __floats2bfloat162_rn(b.z - __bfloat162float(h1.b.x), b.w - __bfloat162float(h1.b.y));
    *(uint2*)(g_img_p2h + off) = make_uint2(h0.u, h1.u);
    *(uint2*)(g_img_p2l + off) = make_uint2(l0.u, l1.u);
}

// ---- main: triangular tiles, fused G1+G2a, async-copy operands ----
__global__ void __launch_bounds__(512)
triplet_fused_kernel(float* __restrict__ out, int n, int nt, int npairs) {
    extern __shared__ char smem[];
    const uint32_t sbase = smem_u32(smem);
    const int tid = threadIdx.x;
    const int wid = tid >> 5;
    const int l   = tid & 31;

    int bi = 0, rem = blockIdx.x;
    while (rem >= nt - bi) { rem -= (nt - bi); bi++; }
    const int bj = bi + rem;
    const bool diag = (bi == bj);

    float* sCbi  = (float*)(smem + SM_CBI);
    float* sCbj  = (float*)(smem + SM_CBJ);
    float* sn1bi = (float*)(smem + SM_N1BI);
    float* sn1bj = (float*)(smem + SM_N1BJ);
    float* sn2bi = (float*)(smem + SM_N2BI);
    float* sn2bj = (float*)(smem + SM_N2BJ);
    unsigned int* srm_bi = (unsigned int*)(smem + SM_RMI);
    unsigned int* srm_bj = (unsigned int*)(smem + SM_RMJ);
    float* ssum = (float*)(smem + SM_SSUM);

    // ---- async-copy the 3 initial operands (p1bi, p1bj, p2bj) ----
    {
        const unsigned char* bh[3] = {g_img_p1h, g_img_p1h, g_img_p2h};
        const unsigned char* bl[3] = {g_img_p1l, g_img_p1l, g_img_p2l};
        const int tix[3] = {bi, bj, bj};
#pragma unroll
        for (int op = 0; op < 3; op++) {
            const unsigned char* gh = bh[op] + (size_t)tix[op] * 2 * CT;
            const unsigned char* gl = bl[op] + (size_t)tix[op] * 2 * CT;
            uint32_t sh = sbase + SM_OPS + op * 4 * CT;
#pragma unroll
            for (int t = 0; t < 2 * CT; t += 8192) {
                cp16(sh + t + tid * 16, gh + t + tid * 16);
                cp16(sh + 2 * CT + t + tid * 16, gl + t + tid * 16);
            }
        }
        CP_COMMIT();
    }

    if (tid < 128) {
        srm_bi[tid] = 0u; srm_bj[tid] = 0u;
        sCbi[tid]  = g_C[bi * TILE + tid];
        sCbj[tid]  = g_C[bj * TILE + tid];
        sn1bi[tid] = g_n1[bi * TILE + tid];
        sn1bj[tid] = g_n1[bj * TILE + tid];
        sn2bi[tid] = g_n2[bi * TILE + tid];
        sn2bj[tid] = g_n2[bj * TILE + tid];
    }
    CP_WAIT0();
    __syncthreads();

    // warp tiling 4x4, warp tile 32x32
    const int wm = wid & 3;
    const int wn = wid >> 2;
    const int qr = l >> 2;
    const int qc = (l & 3) * 2;
    const int arow = wm * 32 + (l & 7) + ((l >> 3) & 1) * 8;
    const int akoff = (l >> 4) * 8;
    const int brow = wn * 32 + (l & 7) + ((l >> 4) << 3);
    const int bkoff = ((l >> 3) & 1) * 8;

    const uint32_t AHI = sbase + SM_OPS + T_P1BI_HI;
    const uint32_t ALO = sbase + SM_OPS + T_P1BI_LO;
    const uint32_t B1HI = sbase + SM_OPS + T_P1BJ_HI;
    const uint32_t B1LO = sbase + SM_OPS + T_P1BJ_LO;
    const uint32_t B2HI = sbase + SM_OPS + T_P2_HI;
    const uint32_t B2LO = sbase + SM_OPS + T_P2_LO;

    float sum = 0.f;
    float acc1[2][4][4], acc2[2][4][4];
#pragma unroll
    for (int mf = 0; mf < 2; mf++)
#pragma unroll
        for (int nf = 0; nf < 4; nf++)
#pragma unroll
            for (int e = 0; e < 4; e++) { acc1[mf][nf][e] = 0.f; acc2[mf][nf][e] = 0.f; }

    // ---- fused G1 (p1bi.p1bj^T) + G2a (p1bi.p2bj^T): shared A fragments ----
#pragma unroll 2
    for (int ks = 0; ks < 8; ks++) {
        const int k0 = ks * 16;
        uint32_t ah[2][4], al[2][4];
#pragma unroll
        for (int mf = 0; mf < 2; mf++) {
            ldsm4(taddr(AHI, arow + mf * 16, k0 + akoff), ah[mf]);
            ldsm4(taddr(ALO, arow + mf * 16, k0 + akoff), al[mf]);
        }
        uint32_t b1h[4][2], b1l[4][2], b2h[4][2], b2l[4][2];
#pragma unroll
        for (int np = 0; np < 2; np++) {
            uint32_t t4[4];
            ldsm4(taddr(B1HI, brow + np * 16, k0 + bkoff), t4);
            b1h[2*np][0]=t4[0]; b1h[2*np][1]=t4[1]; b1h[2*np+1][0]=t4[2]; b1h[2*np+1][1]=t4[3];
            ldsm4(taddr(B1LO, brow + np * 16, k0 + bkoff), t4);
            b1l[2*np][0]=t4[0]; b1l[2*np][1]=t4[1]; b1l[2*np+1][0]=t4[2]; b1l[2*np+1][1]=t4[3];
            ldsm4(taddr(B2HI, brow + np * 16, k0 + bkoff), t4);
            b2h[2*np][0]=t4[0]; b2h[2*np][1]=t4[1]; b2h[2*np+1][0]=t4[2]; b2h[2*np+1][1]=t4[3];
            ldsm4(taddr(B2LO, brow + np * 16, k0 + bkoff), t4);
            b2l[2*np][0]=t4[0]; b2l[2*np][1]=t4[1]; b2l[2*np+1][0]=t4[2]; b2l[2*np+1][1]=t4[3];
        }
#pragma unroll
        for (int mf = 0; mf < 2; mf++)
#pragma unroll
            for (int nf = 0; nf < 4; nf++) {
                MMA(acc1[mf][nf], ah[mf], b1h[nf]);
                MMA(acc2[mf][nf], ah[mf], b2h[nf]);
                MMA(acc1[mf][nf], ah[mf], b1l[nf]);
                MMA(acc2[mf][nf], ah[mf], b2l[nf]);
                MMA(acc1[mf][nf], al[mf], b1h[nf]);
                MMA(acc2[mf][nf], al[mf], b2h[nf]);
            }
    }

    // all warps done reading p2bj before overwriting
    __syncthreads();
    if (!diag) {
        const unsigned char* gh = g_img_p2h + (size_t)bi * 2 * CT;
        const unsigned char* gl = g_img_p2l + (size_t)bi * 2 * CT;
#pragma unroll
        for (int t = 0; t < 2 * CT; t += 8192) {
            cp16(B2HI + t + tid * 16, gh + t + tid * 16);
            cp16(B2LO + t + tid * 16, gl + t + tid * 16);
        }
        CP_COMMIT();
    }

    // ---- epilogues overlap the p2bi async copy ----
    epi_normal(acc1, sCbi, sn1bj, wm, wn, qr, qc, l, diag, srm_bi, sum);
    if (!diag)
        epi_trans(acc1, sCbj, sn1bi, wm, wn, qr, qc, l, srm_bj, sum);
    epi_normal(acc2, sCbi, sn2bj, wm, wn, qr, qc, l, diag, srm_bi, sum);

    // ---- G2b = p1bj . p2bi^T (off-diag only) ----
    if (!diag) {
        CP_WAIT0();
        __syncthreads();
        float acc[2][4][4];
#pragma unroll
        for (int mf = 0; mf < 2; mf++)
#pragma unroll
            for (int nf = 0; nf < 4; nf++)
#pragma unroll
                for (int e = 0; e < 4; e++) acc[mf][nf][e] = 0.f;
#pragma unroll 2
        for (int ks = 0; ks < 8; ks++)
            kstep_mma(B1HI, B1LO, B2HI, B2LO, ks * 16, arow, akoff, brow, bkoff, acc);
        epi_normal(acc, sCbj, sn2bi, wm, wn, qr, qc, l, false, srm_bj, sum);
    }

    // ---- block reduction + global publish ----
#pragma unroll
    for (int m = 16; m; m >>= 1) sum += __shfl_xor_sync(0xffffffffu, sum, m);
    if (l == 0) ssum[wid] = sum;
    __syncthreads();

    if (tid < 128)
        atomicMax(&g_rowmax[bi * TILE + tid], srm_bi[tid]);
    else if (tid < 256 && !diag)
        atomicMax(&g_rowmax[bj * TILE + (tid - 128)], srm_bj[tid - 128]);
    if (tid == 0) {
        float t = 0.f;
#pragma unroll
        for (int w = 0; w < 16; w++) t += ssum[w];
        g_partial[blockIdx.x] = t;
    }
    __threadfence();
    __syncthreads();

    // ---- last-CTA fused finalization ----
    __shared__ unsigned int s_last;
    if (tid == 0) s_last = (atomicAdd(&g_ticket, 1u) == (unsigned)(npairs - 1)) ? 1u : 0u;
    __syncthreads();
    if (!s_last) return;
    __threadfence();

    double smax = 0.0, ssumd = 0.0;
    for (int i = tid; i < n; i += 512) {
        smax += (double)__uint_as_float(g_rowmax[i]);
        g_rowmax[i] = 0u;
    }
    for (int i = tid; i < npairs; i += 512) ssumd += (double)g_partial[i];
#pragma unroll
    for (int m = 16; m; m >>= 1) {
        smax  += __shfl_xor_sync(0xffffffffu, smax, m);
        ssumd += __shfl_xor_sync(0xffffffffu, ssumd, m);
    }
    __shared__ double d1[16], d2[16];
    if (l == 0) { d1[wid] = smax; d2[wid] = ssumd; }
    __syncthreads();
    if (tid == 0) {
        double t1 = 0.0, t2 = 0.0;
#pragma unroll
        for (int w = 0; w < 16; w++) { t1 += d1[w]; t2 += d2[w]; }
        out[0] = (float)(t1 / (double)n);
        out[1] = (float)(t2 / (2.0 * (double)n * (double)(n - 1)));
        g_ticket = 0;
    }
}

extern "C" void kernel_launch(void* const* d_in, const int* in_sizes, int n_in,
                              void* d_out, int out_size) {
    const float* p1 = (const float*)d_in[0];
    const float* p2 = (const float*)d_in[1];
    float* out = (float*)d_out;
    const int n = in_sizes[0] / DIM;            // 4096
    const int nt = n / TILE;                    // 32
    const int npairs = nt * (nt + 1) / 2;       // 528

    cudaFuncSetAttribute(triplet_fused_kernel,
                         cudaFuncAttributeMaxDynamicSharedMemorySize, SMEM_TOTAL);

    prep_kernel<<<n / 32, 1024>>>(p1, p2, n);
    triplet_fused_kernel<<<npairs, 512, SMEM_TOTAL>>>(out, n, nt, npairs);
}

// round 7
// speedup vs baseline: 2.6851x; 1.1301x over previous
#include <cuda_runtime.h>
#include <cuda_bf16.h>
#include <cstdint>

#define MARGIN 0.3f
#define DIM  128
#define TILE 128
#define MAXN 4096
#define MAXT (MAXN / TILE)
#define MAXPAIR (MAXT * (MAXT + 1) / 2)
#define CT   16384                 // image chunk tile: 128 rows x 64 bf16 cols (SW128)

// ---- dynamic smem layout (bytes) ----
#define SM_CBI   0                 // 128 f
#define SM_N1BI  512
#define SM_N2BI  1024
#define SM_CBJH  1536              // 64 f
#define SM_N1BJH 1792
#define SM_N2BJH 2048
#define SM_RMI   2304              // 128 u
#define SM_RMJH  2816              // 64 u
#define SM_SSUM  3072              // 8 f
#define SM_OPS   4096              // 96KB operand region, 1024-aligned
#define SMEM_TOTAL (SM_OPS + 96 * 1024)

// phase1 layout in OPS: A(p1bi full-K) hi: [0,32K) (chunk0,chunk1), lo: [32K,64K)
//                       B chunk buffer [64K,96K): B1H 8K, B1L 8K, B2H 8K, B2L 8K
#define P1_AHI 0
#define P1_ALO (32 * 1024)
#define P1_B1H (64 * 1024)
#define P1_B1L (72 * 1024)
#define P1_B2H (80 * 1024)
#define P1_B2L (88 * 1024)
// phase2 double buffer: buf c at c*48K: A2H 8K, A2L 8K, B2H 16K, B2L 16K
#define P2_BUF(c) ((c) * 48 * 1024)
#define P2_A2H 0
#define P2_A2L (8 * 1024)
#define P2_B2H (16 * 1024)
#define P2_B2L (32 * 1024)

__device__ float g_n1[MAXN], g_n2[MAXN], g_C[MAXN];
__device__ unsigned int g_rowmax[MAXN];      // zero at load; last CTA re-zeros
__device__ float g_partial[2 * MAXPAIR];
__device__ unsigned int g_ticket;            // zero at load; last CTA re-zeros

// pre-swizzled bf16 hi/lo images: [tile][chunk][16KB]
__device__ __align__(16) unsigned char g_img_p1h[MAXT * 2 * CT];
__device__ __align__(16) unsigned char g_img_p1l[MAXT * 2 * CT];
__device__ __align__(16) unsigned char g_img_p2h[MAXT * 2 * CT];
__device__ __align__(16) unsigned char g_img_p2l[MAXT * 2 * CT];

__device__ __forceinline__ uint32_t smem_u32(const void* p) {
    uint32_t a;
    asm("{ .reg .u64 t; cvta.to.shared.u64 t, %1; cvt.u32.u64 %0, t; }" : "=r"(a) : "l"(p));
    return a;
}
__device__ __forceinline__ int swz(int row, int kc) {   // within one chunk tile (row*128B rows)
    int b = row * 128 + kc * 2;
    return b ^ ((b >> 3) & 0x70);
}
__device__ __forceinline__ uint32_t taddrA(uint32_t base0, int row, int kcol) { // full-K, 2 chunks
    return base0 + ((kcol >> 6) << 14) + swz(row, kcol & 63);
}
__device__ __forceinline__ void ldsm4(uint32_t addr, uint32_t r[4]) {
    asm volatile("ldmatrix.sync.aligned.m8n8.x4.shared.b16 {%0,%1,%2,%3}, [%4];"
                 : "=r"(r[0]), "=r"(r[1]), "=r"(r[2]), "=r"(r[3]) : "r"(addr));
}
__device__ __forceinline__ void cp16(uint32_t saddr, const void* g) {
    asm volatile("cp.async.cg.shared.global [%0], [%1], 16;" :: "r"(saddr), "l"(g));
}
#define CP_COMMIT() asm volatile("cp.async.commit_group;" ::: "memory")
#define CP_WAIT0()  asm volatile("cp.async.wait_group 0;" ::: "memory")

#define MMA(d, a, b)                                                               \
    asm volatile("mma.sync.aligned.m16n8k16.row.col.f32.bf16.bf16.f32 "            \
                 "{%0,%1,%2,%3},{%4,%5,%6,%7},{%8,%9},{%0,%1,%2,%3};"              \
                 : "+f"((d)[0]), "+f"((d)[1]), "+f"((d)[2]), "+f"((d)[3])          \
                 : "r"((a)[0]), "r"((a)[1]), "r"((a)[2]), "r"((a)[3]),             \
                   "r"((b)[0]), "r"((b)[1]))

union BU { __nv_bfloat162 b; uint32_t u; };

// generic copy of `bytes` (multiple of 4096) from gsrc to smem with 256 threads
__device__ __forceinline__ void cpa(uint32_t sdst, const unsigned char* gsrc, int bytes, int tid) {
    for (int t = tid * 16; t < bytes; t += 4096) cp16(sdst + t, gsrc + t);
}

__device__ __forceinline__ void epi_normal(
    float (&acc)[2][4][4], const float* Crow, const float* ncol,
    int wm, int wn, int qr, int qc, int l, bool dz, int rbase, int cbase,
    unsigned int* srm, float& sum)
{
    float Cr[2][2], nc[4][2];
#pragma unroll
    for (int mf = 0; mf < 2; mf++) {
        int r0 = wm * 32 + mf * 16 + qr;
        Cr[mf][0] = Crow[r0]; Cr[mf][1] = Crow[r0 + 8];
    }
#pragma unroll
    for (int nf = 0; nf < 4; nf++) {
        int c0 = wn * 32 + nf * 8 + qc;
        nc[nf][0] = ncol[c0]; nc[nf][1] = ncol[c0 + 1];
    }
    float rmax[2][2] = {{0.f, 0.f}, {0.f, 0.f}};
#pragma unroll
    for (int mf = 0; mf < 2; mf++)
#pragma unroll
        for (int nf = 0; nf < 4; nf++)
#pragma unroll
            for (int e = 0; e < 4; e++) {
                int rr = e >> 1, cc = e & 1;
                float v = fmaxf(Cr[mf][rr] - nc[nf][cc] + 2.f * acc[mf][nf][e], 0.f);
                if (dz) {
                    int rl = rbase + wm * 32 + mf * 16 + qr + rr * 8;
                    int cl = cbase + wn * 32 + nf * 8 + qc + cc;
                    if (rl == cl) v = 0.f;
                }
                sum += v;
                rmax[mf][rr] = fmaxf(rmax[mf][rr], v);
            }
#pragma unroll
    for (int m = 1; m <= 2; m <<= 1)
#pragma unroll
        for (int mf = 0; mf < 2; mf++) {
            rmax[mf][0] = fmaxf(rmax[mf][0], __shfl_xor_sync(0xffffffffu, rmax[mf][0], m));
            rmax[mf][1] = fmaxf(rmax[mf][1], __shfl_xor_sync(0xffffffffu, rmax[mf][1], m));
        }
    if ((l & 3) == 0) {
#pragma unroll
        for (int mf = 0; mf < 2; mf++) {
            atomicMax(&srm[wm * 32 + mf * 16 + qr],     __float_as_uint(rmax[mf][0]));
            atomicMax(&srm[wm * 32 + mf * 16 + qr + 8], __float_as_uint(rmax[mf][1]));
        }
    }
}

__device__ __forceinline__ void epi_trans(
    float (&acc)[2][4][4], const float* Ccol, const float* nrow,
    int wm, int wn, int qr, int qc, int l,
    unsigned int* srm, float& sum)
{
    float Ct[4][2], nr[2][2];
#pragma unroll
    for (int nf = 0; nf < 4; nf++) {
        int c0 = wn * 32 + nf * 8 + qc;
        Ct[nf][0] = Ccol[c0]; Ct[nf][1] = Ccol[c0 + 1];
    }
#pragma unroll
    for (int mf = 0; mf < 2; mf++) {
        int r0 = wm * 32 + mf * 16 + qr;
        nr[mf][0] = nrow[r0]; nr[mf][1] = nrow[r0 + 8];
    }
    float cmax[4][2] = {{0.f,0.f},{0.f,0.f},{0.f,0.f},{0.f,0.f}};
#pragma unroll
    for (int mf = 0; mf < 2; mf++)
#pragma unroll
        for (int nf = 0; nf < 4; nf++)
#pragma unroll
            for (int e = 0; e < 4; e++) {
                int rr = e >> 1, cc = e & 1;
                float v = fmaxf(Ct[nf][cc] - nr[mf][rr] + 2.f * acc[mf][nf][e], 0.f);
                sum += v;
                cmax[nf][cc] = fmaxf(cmax[nf][cc], v);
            }
#pragma unroll
    for (int m = 4; m <= 16; m <<= 1)
#pragma unroll
        for (int nf = 0; nf < 4; nf++) {
            cmax[nf][0] = fmaxf(cmax[nf][0], __shfl_xor_sync(0xffffffffu, cmax[nf][0], m));
            cmax[nf][1] = fmaxf(cmax[nf][1], __shfl_xor_sync(0xffffffffu, cmax[nf][1], m));
        }
    if (l < 4) {
#pragma unroll
        for (int nf = 0; nf < 4; nf++) {
            int c0 = wn * 32 + nf * 8 + qc;
            atomicMax(&srm[c0],     __float_as_uint(cmax[nf][0]));
            atomicMax(&srm[c0 + 1], __float_as_uint(cmax[nf][1]));
        }
    }
}

// ---- prep: norms/C + pre-swizzled bf16 hi/lo images ----
__global__ void __launch_bounds__(1024)
prep_kernel(const float* __restrict__ p1, const float* __restrict__ p2, int n) {
    int row = blockIdx.x * 32 + (threadIdx.x >> 5);
    int lane = threadIdx.x & 31;
    if (row >= n) return;
    float4 a = ((const float4*)(p1 + (size_t)row * DIM))[lane];
    float4 b = ((const float4*)(p2 + (size_t)row * DIM))[lane];

    float n1 = a.x*a.x + a.y*a.y + a.z*a.z + a.w*a.w;
    float n2 = b.x*b.x + b.y*b.y + b.z*b.z + b.w*b.w;
    float dx = a.x-b.x, dy = a.y-b.y, dz = a.z-b.z, dw = a.w-b.w;
    float dap = dx*dx + dy*dy + dz*dz + dw*dw;
#pragma unroll
    for (int m = 16; m; m >>= 1) {
        n1 += __shfl_xor_sync(0xffffffffu, n1, m);
        n2 += __shfl_xor_sync(0xffffffffu, n2, m);
        dap += __shfl_xor_sync(0xffffffffu, dap, m);
    }
    if (lane == 0) {
        g_n1[row] = n1; g_n2[row] = n2; g_C[row] = dap - n1 + MARGIN;
    }

    int tile = row >> 7, lr = row & 127;
    int c4 = lane * 4, chunk = c4 >> 6, lc = c4 & 63;
    size_t off = (size_t)(tile * 2 + chunk) * CT + swz(lr, lc);

    BU h0, h1, l0, l1;
    h0.b = __floats2bfloat162_rn(a.x, a.y);
    h1.b = __floats2bfloat162_rn(a.z, a.w);
    l0.b = __floats2bfloat162_rn(a.x - __bfloat162float(h0.b.x), a.y - __bfloat162float(h0.b.y));
    l1.b = __floats2bfloat162_rn(a.z - __bfloat162float(h1.b.x), a.w - __bfloat162float(h1.b.y));
    *(uint2*)(g_img_p1h + off) = make_uint2(h0.u, h1.u);
    *(uint2*)(g_img_p1l + off) = make_uint2(l0.u, l1.u);

    h0.b = __floats2bfloat162_rn(b.x, b.y);
    h1.b = __floats2bfloat162_rn(b.z, b.w);
    l0.b = __floats2bfloat162_rn(b.x - __bfloat162float(h0.b.x), b.y - __bfloat162float(h0.b.y));
    l1.b = __floats2bfloat162_rn(b.z - __bfloat162float(h1.b.x), b.w - __bfloat162float(h1.b.y));
    *(uint2*)(g_img_p2h + off) = make_uint2(h0.u, h1.u);
    *(uint2*)(g_img_p2l + off) = make_uint2(l0.u, l1.u);
}

// ---- main: 256-thread half-tile CTAs (2/SM), triangular pairs ----
__global__ void __launch_bounds__(256, 2)
triplet_half_kernel(float* __restrict__ out, int n, int nt, int nctas) {
    extern __shared__ char smem[];
    const uint32_t sbase = smem_u32(smem);
    const int tid = threadIdx.x;
    const int wid = tid >> 5;
    const int l   = tid & 31;

    const int pairid = blockIdx.x >> 1;
    const int h = blockIdx.x & 1;            // which 64-col half of the bj tile
    int bi = 0, rem = pairid;
    while (rem >= nt - bi) { rem -= (nt - bi); bi++; }
    const int bj = bi + rem;
    const bool diag = (bi == bj);

    float* sCbi   = (float*)(smem + SM_CBI);
    float* sn1bi  = (float*)(smem + SM_N1BI);
    float* sn2bi  = (float*)(smem + SM_N2BI);
    float* sCbjH  = (float*)(smem + SM_CBJH);
    float* sn1bjH = (float*)(smem + SM_N1BJH);
    float* sn2bjH = (float*)(smem + SM_N2BJH);
    unsigned int* srm_bi  = (unsigned int*)(smem + SM_RMI);
    unsigned int* srm_bjH = (unsigned int*)(smem + SM_RMJH);
    float* ssum = (float*)(smem + SM_SSUM);

    const uint32_t OPS = sbase + SM_OPS;

    // ---- phase1 initial loads: A = p1bi full-K hi/lo (64K) + B chunk0 (32K) ----
    cpa(OPS + P1_AHI, g_img_p1h + (size_t)bi * 2 * CT, 32 * 1024, tid);
    cpa(OPS + P1_ALO, g_img_p1l + (size_t)bi * 2 * CT, 32 * 1024, tid);
    {
        size_t hoff = (size_t)(bj * 2 + 0) * CT + h * 8192;
        cpa(OPS + P1_B1H, g_img_p1h + hoff, 8192, tid);
        cpa(OPS + P1_B1L, g_img_p1l + hoff, 8192, tid);
        cpa(OPS + P1_B2H, g_img_p2h + hoff, 8192, tid);
        cpa(OPS + P1_B2L, g_img_p2l + hoff, 8192, tid);
    }
    CP_COMMIT();

    if (tid < 128) {
        srm_bi[tid] = 0u;
        sCbi[tid]  = g_C[bi * TILE + tid];
        sn1bi[tid] = g_n1[bi * TILE + tid];
        sn2bi[tid] = g_n2[bi * TILE + tid];
    } else if (tid < 192) {
        int t = tid - 128;
        srm_bjH[t] = 0u;
        sCbjH[t]  = g_C[bj * TILE + h * 64 + t];
        sn1bjH[t] = g_n1[bj * TILE + h * 64 + t];
        sn2bjH[t] = g_n2[bj * TILE + h * 64 + t];
    }

    // warp tiling phase1: 4 (M) x 2 (N), warp tile 32x32
    const int wm = wid & 3;
    const int wn = wid >> 2;
    const int qr = l >> 2;
    const int qc = (l & 3) * 2;
    const int arow = wm * 32 + (l & 7) + ((l >> 3) & 1) * 8;
    const int akoff = (l >> 4) * 8;
    const int brow = wn * 32 + (l & 7) + ((l >> 4) << 3);
    const int bkoff = ((l >> 3) & 1) * 8;

    float sum = 0.f;
    float acc1[2][4][4], acc2[2][4][4];
#pragma unroll
    for (int mf = 0; mf < 2; mf++)
#pragma unroll
        for (int nf = 0; nf < 4; nf++)
#pragma unroll
            for (int e = 0; e < 4; e++) { acc1[mf][nf][e] = 0.f; acc2[mf][nf][e] = 0.f; }

    CP_WAIT0();
    __syncthreads();

    // ---- phase1: fused G1 (p1bi.p1bjH^T) + G2a (p1bi.p2bjH^T), 2 K-chunks ----
#pragma unroll 1
    for (int c = 0; c < 2; c++) {
        if (c == 1) {
            __syncthreads();        // chunk0 reads done
            size_t hoff = (size_t)(bj * 2 + 1) * CT + h * 8192;
            cpa(OPS + P1_B1H, g_img_p1h + hoff, 8192, tid);
            cpa(OPS + P1_B1L, g_img_p1l + hoff, 8192, tid);
            cpa(OPS + P1_B2H, g_img_p2h + hoff, 8192, tid);
            cpa(OPS + P1_B2L, g_img_p2l + hoff, 8192, tid);
            CP_COMMIT(); CP_WAIT0();
            __syncthreads();
        }
#pragma unroll
        for (int ks = 0; ks < 4; ks++) {
            const int kA = c * 64 + ks * 16;
            const int kB = ks * 16;
            uint32_t ah[2][4], al[2][4];
#pragma unroll
            for (int mf = 0; mf < 2; mf++) {
                ldsm4(taddrA(OPS + P1_AHI, arow + mf * 16, kA + akoff), ah[mf]);
                ldsm4(taddrA(OPS + P1_ALO, arow + mf * 16, kA + akoff), al[mf]);
            }
            uint32_t bh[4][2], bl[4][2];
#pragma unroll
            for (int np = 0; np < 2; np++) {
                uint32_t t4[4];
                ldsm4(OPS + P1_B1H + swz(brow + np * 16, kB + bkoff), t4);
                bh[2*np][0]=t4[0]; bh[2*np][1]=t4[1]; bh[2*np+1][0]=t4[2]; bh[2*np+1][1]=t4[3];
                ldsm4(OPS + P1_B1L + swz(brow + np * 16, kB + bkoff), t4);
                bl[2*np][0]=t4[0]; bl[2*np][1]=t4[1]; bl[2*np+1][0]=t4[2]; bl[2*np+1][1]=t4[3];
            }
#pragma unroll
            for (int mf = 0; mf < 2; mf++)
#pragma unroll
                for (int nf = 0; nf < 4; nf++) {
                    MMA(acc1[mf][nf], ah[mf], bh[nf]);
                    MMA(acc1[mf][nf], ah[mf], bl[nf]);
                    MMA(acc1[mf][nf], al[mf], bh[nf]);
                }
#pragma unroll
            for (int np = 0; np < 2; np++) {
                uint32_t t4[4];
                ldsm4(OPS + P1_B2H + swz(brow + np * 16, kB + bkoff), t4);
                bh[2*np][0]=t4[0]; bh[2*np][1]=t4[1]; bh[2*np+1][0]=t4[2]; bh[2*np+1][1]=t4[3];
                ldsm4(OPS + P1_B2L + swz(brow + np * 16, kB + bkoff), t4);
                bl[2*np][0]=t4[0]; bl[2*np][1]=t4[1]; bl[2*np+1][0]=t4[2]; bl[2*np+1][1]=t4[3];
            }
#pragma unroll
            for (int mf = 0; mf < 2; mf++)
#pragma unroll
                for (int nf = 0; nf < 4; nf++) {
                    MMA(acc2[mf][nf], ah[mf], bh[nf]);
                    MMA(acc2[mf][nf], ah[mf], bl[nf]);
                    MMA(acc2[mf][nf], al[mf], bh[nf]);
                }
        }
    }
    __syncthreads();                // phase1 operand reads done

    // ---- prefetch phase2 buf0 (p1bjH chunk0 as A2, p2bi chunk0 as B2) ----
    if (!diag) {
        size_t a2off = (size_t)(bj * 2 + 0) * CT + h * 8192;
        size_t b2off = (size_t)(bi * 2 + 0) * CT;
        cpa(OPS + P2_BUF(0) + P2_A2H, g_img_p1h + a2off, 8192, tid);
        cpa(OPS + P2_BUF(0) + P2_A2L, g_img_p1l + a2off, 8192, tid);
        cpa(OPS + P2_BUF(0) + P2_B2H, g_img_p2h + b2off, 16384, tid);
        cpa(OPS + P2_BUF(0) + P2_B2L, g_img_p2l + b2off, 16384, tid);
        CP_COMMIT();
    }

    // ---- phase1 epilogues (overlap prefetch) ----
    epi_normal(acc1, sCbi, sn1bjH, wm, wn, qr, qc, l, diag,
               bi * TILE, bj * TILE + h * 64, srm_bi, sum);
    if (!diag)
        epi_trans(acc1, sCbjH, sn1bi, wm, wn, qr, qc, l, srm_bjH, sum);
    epi_normal(acc2, sCbi, sn2bjH, wm, wn, qr, qc, l, diag,
               bi * TILE, bj * TILE + h * 64, srm_bi, sum);

    // ---- phase2: G2b = p1bjH . p2bi^T (off-diag only), double-buffered ----
    if (!diag) {
        const int wm2 = wid & 1;          // M = 64 -> 2 warps
        const int wn2 = wid >> 1;         // N = 128 -> 4 warps
        const int arow2 = wm2 * 32 + (l & 7) + ((l >> 3) & 1) * 8;
        const int brow2 = wn2 * 32 + (l & 7) + ((l >> 4) << 3);

        float accb[2][4][4];
#pragma unroll
        for (int mf = 0; mf < 2; mf++)
#pragma unroll
            for (int nf = 0; nf < 4; nf++)
#pragma unroll
                for (int e = 0; e < 4; e++) accb[mf][nf][e] = 0.f;

        CP_WAIT0();
        __syncthreads();
        // issue buf1 while computing buf0
        {
            size_t a2off = (size_t)(bj * 2 + 1) * CT + h * 8192;
            size_t b2off = (size_t)(bi * 2 + 1) * CT;
            cpa(OPS + P2_BUF(1) + P2_A2H, g_img_p1h + a2off, 8192, tid);
            cpa(OPS + P2_BUF(1) + P2_A2L, g_img_p1l + a2off, 8192, tid);
            cpa(OPS + P2_BUF(1) + P2_B2H, g_img_p2h + b2off, 16384, tid);
            cpa(OPS + P2_BUF(1) + P2_B2L, g_img_p2l + b2off, 16384, tid);
            CP_COMMIT();
        }
#pragma unroll 1
        for (int c = 0; c < 2; c++) {
            if (c == 1) { CP_WAIT0(); __syncthreads(); }
            const uint32_t B = OPS + P2_BUF(c);
#pragma unroll
            for (int ks = 0; ks < 4; ks++) {
                const int k0 = ks * 16;
                uint32_t ah[2][4], al[2][4];
#pragma unroll
                for (int mf = 0; mf < 2; mf++) {
                    ldsm4(B + P2_A2H + swz(arow2 + mf * 16, k0 + akoff), ah[mf]);
                    ldsm4(B + P2_A2L + swz(arow2 + mf * 16, k0 + akoff), al[mf]);
                }
                uint32_t bh[4][2], bl[4][2];
#pragma unroll
                for (int np = 0; np < 2; np++) {
                    uint32_t t4[4];
                    ldsm4(B + P2_B2H + swz(brow2 + np * 16, k0 + bkoff), t4);
                    bh[2*np][0]=t4[0]; bh[2*np][1]=t4[1]; bh[2*np+1][0]=t4[2]; bh[2*np+1][1]=t4[3];
                    ldsm4(B + P2_B2L + swz(brow2 + np * 16, k0 + bkoff), t4);
                    bl[2*np][0]=t4[0]; bl[2*np][1]=t4[1]; bl[2*np+1][0]=t4[2]; bl[2*np+1][1]=t4[3];
                }
#pragma unroll
                for (int mf = 0; mf < 2; mf++)
#pragma unroll
                    for (int nf = 0; nf < 4; nf++) {
                        MMA(accb[mf][nf], ah[mf], bh[nf]);
                        MMA(accb[mf][nf], ah[mf], bl[nf]);
                        MMA(accb[mf][nf], al[mf], bh[nf]);
                    }
            }
        }
        epi_normal(accb, sCbjH, sn2bi, wm2, wn2, qr, qc, l, false, 0, 0, srm_bjH, sum);
    }

    // ---- block reduction + global publish ----
#pragma unroll
    for (int m = 16; m; m >>= 1) sum += __shfl_xor_sync(0xffffffffu, sum, m);
    if (l == 0) ssum[wid] = sum;
    __syncthreads();

    if (tid < 128)
        atomicMax(&g_rowmax[bi * TILE + tid], srm_bi[tid]);
    else if (tid < 192)
        atomicMax(&g_rowmax[bj * TILE + h * 64 + (tid - 128)], srm_bjH[tid - 128]);
    if (tid == 0) {
        float t = 0.f;
#pragma unroll
        for (int w = 0; w < 8; w++) t += ssum[w];
        g_partial[blockIdx.x] = t;
    }
    __threadfence();
    __syncthreads();

    // ---- last-CTA fused finalization ----
    __shared__ unsigned int s_last;
    if (tid == 0) s_last = (atomicAdd(&g_ticket, 1u) == (unsigned)(nctas - 1)) ? 1u : 0u;
    __syncthreads();
    if (!s_last) return;
    __threadfence();

    double smax = 0.0, ssumd = 0.0;
    for (int i = tid; i < n; i += 256) {
        smax += (double)__uint_as_float(g_rowmax[i]);
        g_rowmax[i] = 0u;
    }
    for (int i = tid; i < nctas; i += 256) ssumd += (double)g_partial[i];
#pragma unroll
    for (int m = 16; m; m >>= 1) {
        smax  += __shfl_xor_sync(0xffffffffu, smax, m);
        ssumd += __shfl_xor_sync(0xffffffffu, ssumd, m);
    }
    __shared__ double d1[8], d2[8];
    if (l == 0) { d1[wid] = smax; d2[wid] = ssumd; }
    __syncthreads();
    if (tid == 0) {
        double t1 = 0.0, t2 = 0.0;
#pragma unroll
        for (int w = 0; w < 8; w++) { t1 += d1[w]; t2 += d2[w]; }
        out[0] = (float)(t1 / (double)n);
        out[1] = (float)(t2 / (2.0 * (double)n * (double)(n - 1)));
        g_ticket = 0;
    }
}

extern "C" void kernel_launch(void* const* d_in, const int* in_sizes, int n_in,
                              void* d_out, int out_size) {
    const float* p1 = (const float*)d_in[0];
    const float* p2 = (const float*)d_in[1];
    float* out = (float*)d_out;
    const int n = in_sizes[0] / DIM;            // 4096
    const int nt = n / TILE;                    // 32
    const int npairs = nt * (nt + 1) / 2;       // 528
    const int nctas = npairs * 2;               // 1056

    cudaFuncSetAttribute(triplet_half_kernel,
                         cudaFuncAttributeMaxDynamicSharedMemorySize, SMEM_TOTAL);

    prep_kernel<<<n / 32, 1024>>>(p1, p2, n);
    triplet_half_kernel<<<nctas, 256, SMEM_TOTAL>>>(out, n, nt, nctas);
}

// round 8
// speedup vs baseline: 2.7077x; 1.0084x over previous
#include <cuda_runtime.h>
#include <cuda_bf16.h>
#include <cstdint>

#define MARGIN 0.3f
#define DIM  128
#define TILE 128
#define MAXN 4096
#define MAXT (MAXN / TILE)
#define MAXPAIR (MAXT * (MAXT + 1) / 2)
#define CT   16384                 // image chunk tile: 128 rows x 64 bf16 cols (SW128)

// ---- dynamic smem layout (bytes) ----
#define SM_CBI   0                 // 128 f
#define SM_N1BI  512
#define SM_N2BI  1024
#define SM_CBJH  1536              // 64 f
#define SM_N1BJH 1792
#define SM_N2BJH 2048
#define SM_RMI   2304              // 128 u
#define SM_RMJH  2816              // 64 u
#define SM_SSUM  3072              // 8 f
#define SM_OPS   4096              // 96KB operand region, 1024-aligned
#define SMEM_TOTAL (SM_OPS + 96 * 1024)

// phase1: A(p1bi full-K) hi [0,32K) (c0,c1), lo [32K,64K); B chunk buffers [64K,96K)
#define P1_AHI 0
#define P1_ALO (32 * 1024)
#define P1_B1H (64 * 1024)
#define P1_B1L (72 * 1024)
#define P1_B2H (80 * 1024)
#define P1_B2L (88 * 1024)
// phase2 double buffer: buf c at c*48K: A2H 8K, A2L 8K, B2H 16K, B2L 16K
#define P2_BUF(c) ((c) * 48 * 1024)
#define P2_A2H 0
#define P2_A2L (8 * 1024)
#define P2_B2H (16 * 1024)
#define P2_B2L (32 * 1024)

__device__ float g_n1[MAXN], g_n2[MAXN], g_C[MAXN];
__device__ unsigned int g_rowmax[MAXN];      // zero at load; last CTA re-zeros
__device__ float g_partial[2 * MAXPAIR];
__device__ unsigned int g_ticket;            // zero at load; last CTA re-zeros

// pre-swizzled bf16 hi/lo images: [tile][chunk][16KB]
__device__ __align__(16) unsigned char g_img_p1h[MAXT * 2 * CT];
__device__ __align__(16) unsigned char g_img_p1l[MAXT * 2 * CT];
__device__ __align__(16) unsigned char g_img_p2h[MAXT * 2 * CT];
__device__ __align__(16) unsigned char g_img_p2l[MAXT * 2 * CT];

__device__ __forceinline__ uint32_t smem_u32(const void* p) {
    uint32_t a;
    asm("{ .reg .u64 t; cvta.to.shared.u64 t, %1; cvt.u32.u64 %0, t; }" : "=r"(a) : "l"(p));
    return a;
}
__device__ __forceinline__ int swz(int row, int kc) {   // within one chunk tile
    int b = row * 128 + kc * 2;
    return b ^ ((b >> 3) & 0x70);
}
__device__ __forceinline__ uint32_t taddrA(uint32_t base0, int row, int kcol) { // 2-chunk full-K
    return base0 + ((kcol >> 6) << 14) + swz(row, kcol & 63);
}
__device__ __forceinline__ void ldsm4(uint32_t addr, uint32_t r[4]) {
    asm volatile("ldmatrix.sync.aligned.m8n8.x4.shared.b16 {%0,%1,%2,%3}, [%4];"
                 : "=r"(r[0]), "=r"(r[1]), "=r"(r[2]), "=r"(r[3]) : "r"(addr));
}
__device__ __forceinline__ void cp16(uint32_t saddr, const void* g) {
    asm volatile("cp.async.cg.shared.global [%0], [%1], 16;" :: "r"(saddr), "l"(g));
}
#define CP_COMMIT() asm volatile("cp.async.commit_group;" ::: "memory")
#define CP_WAIT0()  asm volatile("cp.async.wait_group 0;" ::: "memory")
#define CP_WAIT1()  asm volatile("cp.async.wait_group 1;" ::: "memory")

#define MMA(d, a, b)                                                               \
    asm volatile("mma.sync.aligned.m16n8k16.row.col.f32.bf16.bf16.f32 "            \
                 "{%0,%1,%2,%3},{%4,%5,%6,%7},{%8,%9},{%0,%1,%2,%3};"              \
                 : "+f"((d)[0]), "+f"((d)[1]), "+f"((d)[2]), "+f"((d)[3])          \
                 : "r"((a)[0]), "r"((a)[1]), "r"((a)[2]), "r"((a)[3]),             \
                   "r"((b)[0]), "r"((b)[1]))

union BU { __nv_bfloat162 b; uint32_t u; };

__device__ __forceinline__ void cpa(uint32_t sdst, const unsigned char* gsrc, int bytes, int tid) {
    for (int t = tid * 16; t < bytes; t += 4096) cp16(sdst + t, gsrc + t);
}

// 4 consecutive ksteps of one gram: A (2-chunk region, base k = kAbase) x B (single chunk)
__device__ __forceinline__ void group4(
    uint32_t AH, uint32_t AL, uint32_t BH, uint32_t BL, int kAbase,
    int arow, int akoff, int brow, int bkoff, float (&acc)[2][4][4])
{
#pragma unroll
    for (int ks = 0; ks < 4; ks++) {
        const int kA = kAbase + ks * 16;
        const int kB = ks * 16;
        uint32_t ah[2][4], al[2][4];
#pragma unroll
        for (int mf = 0; mf < 2; mf++) {
            ldsm4(taddrA(AH, arow + mf * 16, kA + akoff), ah[mf]);
            ldsm4(taddrA(AL, arow + mf * 16, kA + akoff), al[mf]);
        }
        uint32_t bh[4][2], bl[4][2];
#pragma unroll
        for (int np = 0; np < 2; np++) {
            uint32_t t4[4];
            ldsm4(BH + swz(brow + np * 16, kB + bkoff), t4);
            bh[2*np][0]=t4[0]; bh[2*np][1]=t4[1]; bh[2*np+1][0]=t4[2]; bh[2*np+1][1]=t4[3];
            ldsm4(BL + swz(brow + np * 16, kB + bkoff), t4);
            bl[2*np][0]=t4[0]; bl[2*np][1]=t4[1]; bl[2*np+1][0]=t4[2]; bl[2*np+1][1]=t4[3];
        }
#pragma unroll
        for (int mf = 0; mf < 2; mf++)
#pragma unroll
            for (int nf = 0; nf < 4; nf++) {
                MMA(acc[mf][nf], ah[mf], bh[nf]);
                MMA(acc[mf][nf], ah[mf], bl[nf]);
                MMA(acc[mf][nf], al[mf], bh[nf]);
            }
    }
}

__device__ __forceinline__ void epi_normal(
    float (&acc)[2][4][4], const float* Crow, const float* ncol,
    int wm, int wn, int qr, int qc, int l, bool dz, int rbase, int cbase,
    unsigned int* srm, float& sum)
{
    float Cr[2][2], nc[4][2];
#pragma unroll
    for (int mf = 0; mf < 2; mf++) {
        int r0 = wm * 32 + mf * 16 + qr;
        Cr[mf][0] = Crow[r0]; Cr[mf][1] = Crow[r0 + 8];
    }
#pragma unroll
    for (int nf = 0; nf < 4; nf++) {
        int c0 = wn * 32 + nf * 8 + qc;
        nc[nf][0] = ncol[c0]; nc[nf][1] = ncol[c0 + 1];
    }
    float rmax[2][2] = {{0.f, 0.f}, {0.f, 0.f}};
#pragma unroll
    for (int mf = 0; mf < 2; mf++)
#pragma unroll
        for (int nf = 0; nf < 4; nf++)
#pragma unroll
            for (int e = 0; e < 4; e++) {
                int rr = e >> 1, cc = e & 1;
                float v = fmaxf(Cr[mf][rr] - nc[nf][cc] + 2.f * acc[mf][nf][e], 0.f);
                if (dz) {
                    int rl = rbase + wm * 32 + mf * 16 + qr + rr * 8;
                    int cl = cbase + wn * 32 + nf * 8 + qc + cc;
                    if (rl == cl) v = 0.f;
                }
                sum += v;
                rmax[mf][rr] = fmaxf(rmax[mf][rr], v);
            }
#pragma unroll
    for (int m = 1; m <= 2; m <<= 1)
#pragma unroll
        for (int mf = 0; mf < 2; mf++) {
            rmax[mf][0] = fmaxf(rmax[mf][0], __shfl_xor_sync(0xffffffffu, rmax[mf][0], m));
            rmax[mf][1] = fmaxf(rmax[mf][1], __shfl_xor_sync(0xffffffffu, rmax[mf][1], m));
        }
    if ((l & 3) == 0) {
#pragma unroll
        for (int mf = 0; mf < 2; mf++) {
            atomicMax(&srm[wm * 32 + mf * 16 + qr],     __float_as_uint(rmax[mf][0]));
            atomicMax(&srm[wm * 32 + mf * 16 + qr + 8], __float_as_uint(rmax[mf][1]));
        }
    }
}

__device__ __forceinline__ void epi_trans(
    float (&acc)[2][4][4], const float* Ccol, const float* nrow,
    int wm, int wn, int qr, int qc, int l,
    unsigned int* srm, float& sum)
{
    float Ct[4][2], nr[2][2];
#pragma unroll
    for (int nf = 0; nf < 4; nf++) {
        int c0 = wn * 32 + nf * 8 + qc;
        Ct[nf][0] = Ccol[c0]; Ct[nf][1] = Ccol[c0 + 1];
    }
#pragma unroll
    for (int mf = 0; mf < 2; mf++) {
        int r0 = wm * 32 + mf * 16 + qr;
        nr[mf][0] = nrow[r0]; nr[mf][1] = nrow[r0 + 8];
    }
    float cmax[4][2] = {{0.f,0.f},{0.f,0.f},{0.f,0.f},{0.f,0.f}};
#pragma unroll
    for (int mf = 0; mf < 2; mf++)
#pragma unroll
        for (int nf = 0; nf < 4; nf++)
#pragma unroll
            for (int e = 0; e < 4; e++) {
                int rr = e >> 1, cc = e & 1;
                float v = fmaxf(Ct[nf][cc] - nr[mf][rr] + 2.f * acc[mf][nf][e], 0.f);
                sum += v;
                cmax[nf][cc] = fmaxf(cmax[nf][cc], v);
            }
#pragma unroll
    for (int m = 4; m <= 16; m <<= 1)
#pragma unroll
        for (int nf = 0; nf < 4; nf++) {
            cmax[nf][0] = fmaxf(cmax[nf][0], __shfl_xor_sync(0xffffffffu, cmax[nf][0], m));
            cmax[nf][1] = fmaxf(cmax[nf][1], __shfl_xor_sync(0xffffffffu, cmax[nf][1], m));
        }
    if (l < 4) {
#pragma unroll
        for (int nf = 0; nf < 4; nf++) {
            int c0 = wn * 32 + nf * 8 + qc;
            atomicMax(&srm[c0],     __float_as_uint(cmax[nf][0]));
            atomicMax(&srm[c0 + 1], __float_as_uint(cmax[nf][1]));
        }
    }
}

// ---- prep: norms/C + pre-swizzled bf16 hi/lo images ----
__global__ void __launch_bounds__(1024)
prep_kernel(const float* __restrict__ p1, const float* __restrict__ p2, int n) {
    int row = blockIdx.x * 32 + (threadIdx.x >> 5);
    int lane = threadIdx.x & 31;
    if (row >= n) return;
    float4 a = ((const float4*)(p1 + (size_t)row * DIM))[lane];
    float4 b = ((const float4*)(p2 + (size_t)row * DIM))[lane];

    float n1 = a.x*a.x + a.y*a.y + a.z*a.z + a.w*a.w;
    float n2 = b.x*b.x + b.y*b.y + b.z*b.z + b.w*b.w;
    float dx = a.x-b.x, dy = a.y-b.y, dz = a.z-b.z, dw = a.w-b.w;
    float dap = dx*dx + dy*dy + dz*dz + dw*dw;
#pragma unroll
    for (int m = 16; m; m >>= 1) {
        n1 += __shfl_xor_sync(0xffffffffu, n1, m);
        n2 += __shfl_xor_sync(0xffffffffu, n2, m);
        dap += __shfl_xor_sync(0xffffffffu, dap, m);
    }
    if (lane == 0) {
        g_n1[row] = n1; g_n2[row] = n2; g_C[row] = dap - n1 + MARGIN;
    }

    int tile = row >> 7, lr = row & 127;
    int c4 = lane * 4, chunk = c4 >> 6, lc = c4 & 63;
    size_t off = (size_t)(tile * 2 + chunk) * CT + swz(lr, lc);

    BU h0, h1, l0, l1;
    h0.b = __floats2bfloat162_rn(a.x, a.y);
    h1.b = __floats2bfloat162_rn(a.z, a.w);
    l0.b = __floats2bfloat162_rn(a.x - __bfloat162float(h0.b.x), a.y - __bfloat162float(h0.b.y));
    l1.b = __floats2bfloat162_rn(a.z - __bfloat162float(h1.b.x), a.w - __bfloat162float(h1.b.y));
    *(uint2*)(g_img_p1h + off) = make_uint2(h0.u, h1.u);
    *(uint2*)(g_img_p1l + off) = make_uint2(l0.u, l1.u);

    h0.b = __floats2bfloat162_rn(b.x, b.y);
    h1.b = __floats2bfloat162_rn(b.z, b.w);
    l0.b = __floats2bfloat162_rn(b.x - __bfloat162float(h0.b.x), b.y - __bfloat162float(h0.b.y));
    l1.b = __floats2bfloat162_rn(b.z - __bfloat162float(h1.b.x), b.w - __bfloat162float(h1.b.y));
    *(uint2*)(g_img_p2h + off) = make_uint2(h0.u, h1.u);
    *(uint2*)(g_img_p2l + off) = make_uint2(l0.u, l1.u);
}

// ---- main: 256-thread half-tile CTAs (2/SM), pipelined chunk streaming ----
__global__ void __launch_bounds__(256, 2)
triplet_half_kernel(float* __restrict__ out, int n, int nt, int nctas) {
    extern __shared__ char smem[];
    const uint32_t sbase = smem_u32(smem);
    const int tid = threadIdx.x;
    const int wid = tid >> 5;
    const int l   = tid & 31;

    const int pairid = blockIdx.x >> 1;
    const int h = blockIdx.x & 1;            // which 64-col half of the bj tile
    int bi = 0, rem = pairid;
    while (rem >= nt - bi) { rem -= (nt - bi); bi++; }
    const int bj = bi + rem;
    const bool diag = (bi == bj);

    float* sCbi   = (float*)(smem + SM_CBI);
    float* sn1bi  = (float*)(smem + SM_N1BI);
    float* sn2bi  = (float*)(smem + SM_N2BI);
    float* sCbjH  = (float*)(smem + SM_CBJH);
    float* sn1bjH = (float*)(smem + SM_N1BJH);
    float* sn2bjH = (float*)(smem + SM_N2BJH);
    unsigned int* srm_bi  = (unsigned int*)(smem + SM_RMI);
    unsigned int* srm_bjH = (unsigned int*)(smem + SM_RMJH);
    float* ssum = (float*)(smem + SM_SSUM);

    const uint32_t OPS = sbase + SM_OPS;
    const size_t hoff0 = (size_t)(bj * 2 + 0) * CT + h * 8192;
    const size_t hoff1 = (size_t)(bj * 2 + 1) * CT + h * 8192;

    // ---- pipelined initial loads: g0 = A-c0 + B-c0 (64K), g1 = A-c1 (32K) ----
    cpa(OPS + P1_AHI, g_img_p1h + (size_t)(bi * 2 + 0) * CT, CT, tid);
    cpa(OPS + P1_ALO, g_img_p1l + (size_t)(bi * 2 + 0) * CT, CT, tid);
    cpa(OPS + P1_B1H, g_img_p1h + hoff0, 8192, tid);
    cpa(OPS + P1_B1L, g_img_p1l + hoff0, 8192, tid);
    cpa(OPS + P1_B2H, g_img_p2h + hoff0, 8192, tid);
    cpa(OPS + P1_B2L, g_img_p2l + hoff0, 8192, tid);
    CP_COMMIT();                                                    // g0
    cpa(OPS + P1_AHI + CT, g_img_p1h + (size_t)(bi * 2 + 1) * CT, CT, tid);
    cpa(OPS + P1_ALO + CT, g_img_p1l + (size_t)(bi * 2 + 1) * CT, CT, tid);
    CP_COMMIT();                                                    // g1

    if (tid < 128) {
        srm_bi[tid] = 0u;
        sCbi[tid]  = g_C[bi * TILE + tid];
        sn1bi[tid] = g_n1[bi * TILE + tid];
        sn2bi[tid] = g_n2[bi * TILE + tid];
    } else if (tid < 192) {
        int t = tid - 128;
        srm_bjH[t] = 0u;
        sCbjH[t]  = g_C[bj * TILE + h * 64 + t];
        sn1bjH[t] = g_n1[bj * TILE + h * 64 + t];
        sn2bjH[t] = g_n2[bj * TILE + h * 64 + t];
    }

    // warp tiling phase1: 4 (M) x 2 (N), warp tile 32x32
    const int wm = wid & 3;
    const int wn = wid >> 2;
    const int qr = l >> 2;
    const int qc = (l & 3) * 2;
    const int arow = wm * 32 + (l & 7) + ((l >> 3) & 1) * 8;
    const int akoff = (l >> 4) * 8;
    const int brow = wn * 32 + (l & 7) + ((l >> 4) << 3);
    const int bkoff = ((l >> 3) & 1) * 8;

    float sum = 0.f;
    float acc1[2][4][4], acc2[2][4][4];
#pragma unroll
    for (int mf = 0; mf < 2; mf++)
#pragma unroll
        for (int nf = 0; nf < 4; nf++)
#pragma unroll
            for (int e = 0; e < 4; e++) { acc1[mf][nf][e] = 0.f; acc2[mf][nf][e] = 0.f; }

    CP_WAIT1();                 // g0 ready (A-c1 may still fly)
    __syncthreads();

    // ---- phase1 pipelined: [acc1 c0][ld B1c1][acc2 c0][ld B2c1][acc1 c1][acc2 c1] ----
    group4(OPS + P1_AHI, OPS + P1_ALO, OPS + P1_B1H, OPS + P1_B1L, 0,
           arow, akoff, brow, bkoff, acc1);
    __syncthreads();            // B1-c0 reads done
    cpa(OPS + P1_B1H, g_img_p1h + hoff1, 8192, tid);
    cpa(OPS + P1_B1L, g_img_p1l + hoff1, 8192, tid);
    CP_COMMIT();                                                    // g2
    group4(OPS + P1_AHI, OPS + P1_ALO, OPS + P1_B2H, OPS + P1_B2L, 0,
           arow, akoff, brow, bkoff, acc2);
    __syncthreads();            // B2-c0 reads done
    cpa(OPS + P1_B2H, g_img_p2h + hoff1, 8192, tid);
    cpa(OPS + P1_B2L, g_img_p2l + hoff1, 8192, tid);
    CP_COMMIT();                                                    // g3
    CP_WAIT1();                 // g1 (A-c1) + g2 (B1-c1) done; g3 may fly
    __syncthreads();
    group4(OPS + P1_AHI, OPS + P1_ALO, OPS + P1_B1H, OPS + P1_B1L, 64,
           arow, akoff, brow, bkoff, acc1);
    CP_WAIT0();                 // g3 (B2-c1) done
    __syncthreads();
    group4(OPS + P1_AHI, OPS + P1_ALO, OPS + P1_B2H, OPS + P1_B2L, 64,
           arow, akoff, brow, bkoff, acc2);
    __syncthreads();            // all phase1 operand reads done

    // ---- prefetch phase2 buf0 (overwrites A region), overlap epilogues ----
    if (!diag) {
        cpa(OPS + P2_BUF(0) + P2_A2H, g_img_p1h + hoff0, 8192, tid);
        cpa(OPS + P2_BUF(0) + P2_A2L, g_img_p1l + hoff0, 8192, tid);
        cpa(OPS + P2_BUF(0) + P2_B2H, g_img_p2h + (size_t)(bi * 2 + 0) * CT, CT, tid);
        cpa(OPS + P2_BUF(0) + P2_B2L, g_img_p2l + (size_t)(bi * 2 + 0) * CT, CT, tid);
        CP_COMMIT();
    }

    epi_normal(acc1, sCbi, sn1bjH, wm, wn, qr, qc, l, diag,
               bi * TILE, bj * TILE + h * 64, srm_bi, sum);
    if (!diag)
        epi_trans(acc1, sCbjH, sn1bi, wm, wn, qr, qc, l, srm_bjH, sum);
    epi_normal(acc2, sCbi, sn2bjH, wm, wn, qr, qc, l, diag,
               bi * TILE, bj * TILE + h * 64, srm_bi, sum);

    // ---- phase2: G2b = p1bjH . p2bi^T (off-diag only), double-buffered ----
    if (!diag) {
        const int wm2 = wid & 1;          // M = 64 -> 2 warps
        const int wn2 = wid >> 1;         // N = 128 -> 4 warps
        const int arow2 = wm2 * 32 + (l & 7) + ((l >> 3) & 1) * 8;
        const int brow2 = wn2 * 32 + (l & 7) + ((l >> 4) << 3);

        float accb[2][4][4];
#pragma unroll
        for (int mf = 0; mf < 2; mf++)
#pragma unroll
            for (int nf = 0; nf < 4; nf++)
#pragma unroll
                for (int e = 0; e < 4; e++) accb[mf][nf][e] = 0.f;

        CP_WAIT0();
        __syncthreads();
        // issue buf1 while computing buf0 (disjoint regions)
        cpa(OPS + P2_BUF(1) + P2_A2H, g_img_p1h + hoff1, 8192, tid);
        cpa(OPS + P2_BUF(1) + P2_A2L, g_img_p1l + hoff1, 8192, tid);
        cpa(OPS + P2_BUF(1) + P2_B2H, g_img_p2h + (size_t)(bi * 2 + 1) * CT, CT, tid);
        cpa(OPS + P2_BUF(1) + P2_B2L, g_img_p2l + (size_t)(bi * 2 + 1) * CT, CT, tid);
        CP_COMMIT();

#pragma unroll 1
        for (int c = 0; c < 2; c++) {
            if (c == 1) { CP_WAIT0(); __syncthreads(); }
            const uint32_t B = OPS + P2_BUF(c);
            group4(B + P2_A2H, B + P2_A2L, B + P2_B2H, B + P2_B2L, 0,
                   arow2, akoff, brow2, bkoff, accb);
        }
        epi_normal(accb, sCbjH, sn2bi, wm2, wn2, qr, qc, l, false, 0, 0, srm_bjH, sum);
    }

    // ---- block reduction + global publish ----
#pragma unroll
    for (int m = 16; m; m >>= 1) sum += __shfl_xor_sync(0xffffffffu, sum, m);
    if (l == 0) ssum[wid] = sum;
    __syncthreads();

    if (tid < 128)
        atomicMax(&g_rowmax[bi * TILE + tid], srm_bi[tid]);
    else if (tid < 192)
        atomicMax(&g_rowmax[bj * TILE + h * 64 + (tid - 128)], srm_bjH[tid - 128]);
    if (tid == 0) {
        float t = 0.f;
#pragma unroll
        for (int w = 0; w < 8; w++) t += ssum[w];
        g_partial[blockIdx.x] = t;
    }
    __threadfence();
    __syncthreads();

    // ---- last-CTA fused finalization ----
    __shared__ unsigned int s_last;
    if (tid == 0) s_last = (atomicAdd(&g_ticket, 1u) == (unsigned)(nctas - 1)) ? 1u : 0u;
    __syncthreads();
    if (!s_last) return;
    __threadfence();

    double smax = 0.0, ssumd = 0.0;
    for (int i = tid; i < n; i += 256) {
        smax += (double)__uint_as_float(g_rowmax[i]);
        g_rowmax[i] = 0u;
    }
    for (int i = tid; i < nctas; i += 256) ssumd += (double)g_partial[i];
#pragma unroll
    for (int m = 16; m; m >>= 1) {
        smax  += __shfl_xor_sync(0xffffffffu, smax, m);
        ssumd += __shfl_xor_sync(0xffffffffu, ssumd, m);
    }
    __shared__ double d1[8], d2[8];
    if (l == 0) { d1[wid] = smax; d2[wid] = ssumd; }
    __syncthreads();
    if (tid == 0) {
        double t1 = 0.0, t2 = 0.0;
#pragma unroll
        for (int w = 0; w < 8; w++) { t1 += d1[w]; t2 += d2[w]; }
        out[0] = (float)(t1 / (double)n);
        out[1] = (float)(t2 / (2.0 * (double)n * (double)(n - 1)));
        g_ticket = 0;
    }
}

extern "C" void kernel_launch(void* const* d_in, const int* in_sizes, int n_in,
                              void* d_out, int out_size) {
    const float* p1 = (const float*)d_in[0];
    const float* p2 = (const float*)d_in[1];
    float* out = (float*)d_out;
    const int n = in_sizes[0] / DIM;            // 4096
    const int nt = n / TILE;                    // 32
    const int npairs = nt * (nt + 1) / 2;       // 528
    const int nctas = npairs * 2;               // 1056

    cudaFuncSetAttribute(triplet_half_kernel,
                         cudaFuncAttributeMaxDynamicSharedMemorySize, SMEM_TOTAL);

    prep_kernel<<<n / 32, 1024>>>(p1, p2, n);
    triplet_half_kernel<<<nctas, 256, SMEM_TOTAL>>>(out, n, nt, nctas);
}

// round 9
// speedup vs baseline: 2.8344x; 1.0468x over previous
#include <cuda_runtime.h>
#include <cuda_bf16.h>
#include <cstdint>

#define MARGIN 0.3f
#define DIM  128
#define TILE 128
#define MAXN 4096
#define MAXT (MAXN / TILE)
#define MAXPAIR (MAXT * (MAXT + 1) / 2)
#define CT   16384                 // image chunk tile: 128 rows x 64 bf16 cols (SW128)

// ---- dynamic smem layout (bytes) ----
#define SM_CBI   0                 // 128 f
#define SM_N1BI  512
#define SM_N2BI  1024
#define SM_CBJH  1536              // 64 f
#define SM_N1BJH 1792
#define SM_N2BJH 2048
#define SM_RMI   2304              // 128 u
#define SM_RMJH  2816              // 64 u
#define SM_SSUM  3072              // 8 f
#define SM_OPS   4096              // 96KB operand region, 1024-aligned
#define SMEM_TOTAL (SM_OPS + 96 * 1024)

// phase1: A(p1bi full-K) hi [0,32K) (c0,c1), lo [32K,64K); B chunk buffers [64K,96K)
#define P1_AHI 0
#define P1_ALO (32 * 1024)
#define P1_B1H (64 * 1024)
#define P1_B1L (72 * 1024)
#define P1_B2H (80 * 1024)
#define P1_B2L (88 * 1024)
// phase2 double buffer: buf c at c*48K: A2H 8K, A2L 8K, B2H 16K, B2L 16K
#define P2_BUF(c) ((c) * 48 * 1024)
#define P2_A2H 0
#define P2_A2L (8 * 1024)
#define P2_B2H (16 * 1024)
#define P2_B2L (32 * 1024)

__device__ float g_n1[MAXN], g_n2[MAXN], g_C[MAXN];
__device__ unsigned int g_rowmax[MAXN];      // zero at load; finalizer re-zeros
__device__ float g_partial[2 * MAXPAIR];
__device__ unsigned int g_work;              // work ticket; finalizer re-zeros
__device__ unsigned int g_done;              // CTA done counter; finalizer re-zeros

// pre-swizzled bf16 hi/lo images: [tile][chunk][16KB]
__device__ __align__(16) unsigned char g_img_p1h[MAXT * 2 * CT];
__device__ __align__(16) unsigned char g_img_p1l[MAXT * 2 * CT];
__device__ __align__(16) unsigned char g_img_p2h[MAXT * 2 * CT];
__device__ __align__(16) unsigned char g_img_p2l[MAXT * 2 * CT];

__device__ __forceinline__ uint32_t smem_u32(const void* p) {
    uint32_t a;
    asm("{ .reg .u64 t; cvta.to.shared.u64 t, %1; cvt.u32.u64 %0, t; }" : "=r"(a) : "l"(p));
    return a;
}
__device__ __forceinline__ int swz(int row, int kc) {
    int b = row * 128 + kc * 2;
    return b ^ ((b >> 3) & 0x70);
}
__device__ __forceinline__ uint32_t taddrA(uint32_t base0, int row, int kcol) {
    return base0 + ((kcol >> 6) << 14) + swz(row, kcol & 63);
}
__device__ __forceinline__ void ldsm4(uint32_t addr, uint32_t r[4]) {
    asm volatile("ldmatrix.sync.aligned.m8n8.x4.shared.b16 {%0,%1,%2,%3}, [%4];"
                 : "=r"(r[0]), "=r"(r[1]), "=r"(r[2]), "=r"(r[3]) : "r"(addr));
}
__device__ __forceinline__ void cp16(uint32_t saddr, const void* g) {
    asm volatile("cp.async.cg.shared.global [%0], [%1], 16;" :: "r"(saddr), "l"(g));
}
#define CP_COMMIT() asm volatile("cp.async.commit_group;" ::: "memory")
#define CP_WAIT0()  asm volatile("cp.async.wait_group 0;" ::: "memory")
#define CP_WAIT1()  asm volatile("cp.async.wait_group 1;" ::: "memory")

#define MMA(d, a, b)                                                               \
    asm volatile("mma.sync.aligned.m16n8k16.row.col.f32.bf16.bf16.f32 "            \
                 "{%0,%1,%2,%3},{%4,%5,%6,%7},{%8,%9},{%0,%1,%2,%3};"              \
                 : "+f"((d)[0]), "+f"((d)[1]), "+f"((d)[2]), "+f"((d)[3])          \
                 : "r"((a)[0]), "r"((a)[1]), "r"((a)[2]), "r"((a)[3]),             \
                   "r"((b)[0]), "r"((b)[1]))

union BU { __nv_bfloat162 b; uint32_t u; };

__device__ __forceinline__ void cpa(uint32_t sdst, const unsigned char* gsrc, int bytes, int tid) {
    for (int t = tid * 16; t < bytes; t += 4096) cp16(sdst + t, gsrc + t);
}

__device__ __forceinline__ void decode(int w, int nt, int& bi, int& bj, int& h) {
    int pairid = w >> 1;
    h = w & 1;
    bi = 0;
    int rem = pairid;
    while (rem >= nt - bi) { rem -= (nt - bi); bi++; }
    bj = bi + rem;
}

// issue the phase1 prologue loads for item (bi,bj,h): g0 = A-c0 + B-c0, g1 = A-c1
__device__ __forceinline__ void load_item(uint32_t OPS, int bi, int bj, int h, int tid) {
    size_t hoff0 = (size_t)(bj * 2 + 0) * CT + h * 8192;
    cpa(OPS + P1_AHI, g_img_p1h + (size_t)(bi * 2 + 0) * CT, CT, tid);
    cpa(OPS + P1_ALO, g_img_p1l + (size_t)(bi * 2 + 0) * CT, CT, tid);
    cpa(OPS + P1_B1H, g_img_p1h + hoff0, 8192, tid);
    cpa(OPS + P1_B1L, g_img_p1l + hoff0, 8192, tid);
    cpa(OPS + P1_B2H, g_img_p2h + hoff0, 8192, tid);
    cpa(OPS + P1_B2L, g_img_p2l + hoff0, 8192, tid);
    CP_COMMIT();                                                   // g0
    cpa(OPS + P1_AHI + CT, g_img_p1h + (size_t)(bi * 2 + 1) * CT, CT, tid);
    cpa(OPS + P1_ALO + CT, g_img_p1l + (size_t)(bi * 2 + 1) * CT, CT, tid);
    CP_COMMIT();                                                   // g1
}

// 4 consecutive ksteps of one gram
__device__ __forceinline__ void group4(
    uint32_t AH, uint32_t AL, uint32_t BH, uint32_t BL, int kAbase,
    int arow, int akoff, int brow, int bkoff, float (&acc)[2][4][4])
{
#pragma unroll
    for (int ks = 0; ks < 4; ks++) {
        const int kA = kAbase + ks * 16;
        const int kB = ks * 16;
        uint32_t ah[2][4], al[2][4];
#pragma unroll
        for (int mf = 0; mf < 2; mf++) {
            ldsm4(taddrA(AH, arow + mf * 16, kA + akoff), ah[mf]);
            ldsm4(taddrA(AL, arow + mf * 16, kA + akoff), al[mf]);
        }
        uint32_t bh[4][2], bl[4][2];
#pragma unroll
        for (int np = 0; np < 2; np++) {
            uint32_t t4[4];
            ldsm4(BH + swz(brow + np * 16, kB + bkoff), t4);
            bh[2*np][0]=t4[0]; bh[2*np][1]=t4[1]; bh[2*np+1][0]=t4[2]; bh[2*np+1][1]=t4[3];
            ldsm4(BL + swz(brow + np * 16, kB + bkoff), t4);
            bl[2*np][0]=t4[0]; bl[2*np][1]=t4[1]; bl[2*np+1][0]=t4[2]; bl[2*np+1][1]=t4[3];
        }
#pragma unroll
        for (int mf = 0; mf < 2; mf++)
#pragma unroll
            for (int nf = 0; nf < 4; nf++) {
                MMA(acc[mf][nf], ah[mf], bh[nf]);
                MMA(acc[mf][nf], ah[mf], bl[nf]);
                MMA(acc[mf][nf], al[mf], bh[nf]);
            }
    }
}

__device__ __forceinline__ void epi_normal(
    float (&acc)[2][4][4], const float* Crow, const float* ncol,
    int wm, int wn, int qr, int qc, int l, bool dz, int rbase, int cbase,
    unsigned int* srm, float& sum)
{
    float Cr[2][2], nc[4][2];
#pragma unroll
    for (int mf = 0; mf < 2; mf++) {
        int r0 = wm * 32 + mf * 16 + qr;
        Cr[mf][0] = Crow[r0]; Cr[mf][1] = Crow[r0 + 8];
    }
#pragma unroll
    for (int nf = 0; nf < 4; nf++) {
        int c0 = wn * 32 + nf * 8 + qc;
        nc[nf][0] = ncol[c0]; nc[nf][1] = ncol[c0 + 1];
    }
    float rmax[2][2] = {{0.f, 0.f}, {0.f, 0.f}};
#pragma unroll
    for (int mf = 0; mf < 2; mf++)
#pragma unroll
        for (int nf = 0; nf < 4; nf++)
#pragma unroll
            for (int e = 0; e < 4; e++) {
                int rr = e >> 1, cc = e & 1;
                float v = fmaxf(Cr[mf][rr] - nc[nf][cc] + 2.f * acc[mf][nf][e], 0.f);
                if (dz) {
                    int rl = rbase + wm * 32 + mf * 16 + qr + rr * 8;
                    int cl = cbase + wn * 32 + nf * 8 + qc + cc;
                    if (rl == cl) v = 0.f;
                }
                sum += v;
                rmax[mf][rr] = fmaxf(rmax[mf][rr], v);
            }
#pragma unroll
    for (int m = 1; m <= 2; m <<= 1)
#pragma unroll
        for (int mf = 0; mf < 2; mf++) {
            rmax[mf][0] = fmaxf(rmax[mf][0], __shfl_xor_sync(0xffffffffu, rmax[mf][0], m));
            rmax[mf][1] = fmaxf(rmax[mf][1], __shfl_xor_sync(0xffffffffu, rmax[mf][1], m));
        }
    if ((l & 3) == 0) {
#pragma unroll
        for (int mf = 0; mf < 2; mf++) {
            atomicMax(&srm[wm * 32 + mf * 16 + qr],     __float_as_uint(rmax[mf][0]));
            atomicMax(&srm[wm * 32 + mf * 16 + qr + 8], __float_as_uint(rmax[mf][1]));
        }
    }
}

__device__ __forceinline__ void epi_trans(
    float (&acc)[2][4][4], const float* Ccol, const float* nrow,
    int wm, int wn, int qr, int qc, int l,
    unsigned int* srm, float& sum)
{
    float Ct[4][2], nr[2][2];
#pragma unroll
    for (int nf = 0; nf < 4; nf++) {
        int c0 = wn * 32 + nf * 8 + qc;
        Ct[nf][0] = Ccol[c0]; Ct[nf][1] = Ccol[c0 + 1];
    }
#pragma unroll
    for (int mf = 0; mf < 2; mf++) {
        int r0 = wm * 32 + mf * 16 + qr;
        nr[mf][0] = nrow[r0]; nr[mf][1] = nrow[r0 + 8];
    }
    float cmax[4][2] = {{0.f,0.f},{0.f,0.f},{0.f,0.f},{0.f,0.f}};
#pragma unroll
    for (int mf = 0; mf < 2; mf++)
#pragma unroll
        for (int nf = 0; nf < 4; nf++)
#pragma unroll
            for (int e = 0; e < 4; e++) {
                int rr = e >> 1, cc = e & 1;
                float v = fmaxf(Ct[nf][cc] - nr[mf][rr] + 2.f * acc[mf][nf][e], 0.f);
                sum += v;
                cmax[nf][cc] = fmaxf(cmax[nf][cc], v);
            }
#pragma unroll
    for (int m = 4; m <= 16; m <<= 1)
#pragma unroll
        for (int nf = 0; nf < 4; nf++) {
            cmax[nf][0] = fmaxf(cmax[nf][0], __shfl_xor_sync(0xffffffffu, cmax[nf][0], m));
            cmax[nf][1] = fmaxf(cmax[nf][1], __shfl_xor_sync(0xffffffffu, cmax[nf][1], m));
        }
    if (l < 4) {
#pragma unroll
        for (int nf = 0; nf < 4; nf++) {
            int c0 = wn * 32 + nf * 8 + qc;
            atomicMax(&srm[c0],     __float_as_uint(cmax[nf][0]));
            atomicMax(&srm[c0 + 1], __float_as_uint(cmax[nf][1]));
        }
    }
}

// ---- prep: norms/C + pre-swizzled bf16 hi/lo images ----
__global__ void __launch_bounds__(256)
prep_kernel(const float* __restrict__ p1, const float* __restrict__ p2, int n) {
    int row = blockIdx.x * 8 + (threadIdx.x >> 5);
    int lane = threadIdx.x & 31;
    if (row >= n) return;
    float4 a = ((const float4*)(p1 + (size_t)row * DIM))[lane];
    float4 b = ((const float4*)(p2 + (size_t)row * DIM))[lane];

    float n1 = a.x*a.x + a.y*a.y + a.z*a.z + a.w*a.w;
    float n2 = b.x*b.x + b.y*b.y + b.z*b.z + b.w*b.w;
    float dx = a.x-b.x, dy = a.y-b.y, dz = a.z-b.z, dw = a.w-b.w;
    float dap = dx*dx + dy*dy + dz*dz + dw*dw;
#pragma unroll
    for (int m = 16; m; m >>= 1) {
        n1 += __shfl_xor_sync(0xffffffffu, n1, m);
        n2 += __shfl_xor_sync(0xffffffffu, n2, m);
        dap += __shfl_xor_sync(0xffffffffu, dap, m);
    }
    if (lane == 0) {
        g_n1[row] = n1; g_n2[row] = n2; g_C[row] = dap - n1 + MARGIN;
    }

    int tile = row >> 7, lr = row & 127;
    int c4 = lane * 4, chunk = c4 >> 6, lc = c4 & 63;
    size_t off = (size_t)(tile * 2 + chunk) * CT + swz(lr, lc);

    BU h0, h1, l0, l1;
    h0.b = __floats2bfloat162_rn(a.x, a.y);
    h1.b = __floats2bfloat162_rn(a.z, a.w);
    l0.b = __floats2bfloat162_rn(a.x - __bfloat162float(h0.b.x), a.y - __bfloat162float(h0.b.y));
    l1.b = __floats2bfloat162_rn(a.z - __bfloat162float(h1.b.x), a.w - __bfloat162float(h1.b.y));
    *(uint2*)(g_img_p1h + off) = make_uint2(h0.u, h1.u);
    *(uint2*)(g_img_p1l + off) = make_uint2(l0.u, l1.u);

    h0.b = __floats2bfloat162_rn(b.x, b.y);
    h1.b = __floats2bfloat162_rn(b.z, b.w);
    l0.b = __floats2bfloat162_rn(b.x - __bfloat162float(h0.b.x), b.y - __bfloat162float(h0.b.y));
    l1.b = __floats2bfloat162_rn(b.z - __bfloat162float(h1.b.x), b.w - __bfloat162float(h1.b.y));
    *(uint2*)(g_img_p2h + off) = make_uint2(h0.u, h1.u);
    *(uint2*)(g_img_p2l + off) = make_uint2(l0.u, l1.u);
}

// ---- main: persistent CTAs, dynamic work stealing, cross-item prefetch ----
__global__ void __launch_bounds__(256, 2)
triplet_persist_kernel(float* __restrict__ out, int n, int nt, int nwork) {
    extern __shared__ char smem[];
    const uint32_t sbase = smem_u32(smem);
    const int tid = threadIdx.x;
    const int wid = tid >> 5;
    const int l   = tid & 31;

    float* sCbi   = (float*)(smem + SM_CBI);
    float* sn1bi  = (float*)(smem + SM_N1BI);
    float* sn2bi  = (float*)(smem + SM_N2BI);
    float* sCbjH  = (float*)(smem + SM_CBJH);
    float* sn1bjH = (float*)(smem + SM_N1BJH);
    float* sn2bjH = (float*)(smem + SM_N2BJH);
    unsigned int* srm_bi  = (unsigned int*)(smem + SM_RMI);
    unsigned int* srm_bjH = (unsigned int*)(smem + SM_RMJH);
    float* ssum = (float*)(smem + SM_SSUM);
    const uint32_t OPS = sbase + SM_OPS;

    __shared__ int s_w;

    // warp tiling constants
    const int wm = wid & 3;
    const int wn = wid >> 2;
    const int qr = l >> 2;
    const int qc = (l & 3) * 2;
    const int arow = wm * 32 + (l & 7) + ((l >> 3) & 1) * 8;
    const int akoff = (l >> 4) * 8;
    const int brow = wn * 32 + (l & 7) + ((l >> 4) << 3);
    const int bkoff = ((l >> 3) & 1) * 8;
    const int wm2 = wid & 1;
    const int wn2 = wid >> 1;
    const int arow2 = wm2 * 32 + (l & 7) + ((l >> 3) & 1) * 8;
    const int brow2 = wn2 * 32 + (l & 7) + ((l >> 4) << 3);

    if (tid == 0) s_w = (int)atomicAdd(&g_work, 1u);
    __syncthreads();
    int w = s_w;
    if (w < nwork) {
        int bi, bj, h; decode(w, nt, bi, bj, h);
        load_item(OPS, bi, bj, h, tid);                 // g0, g1 outstanding
    }

    while (w < nwork) {
        int bi, bj, h; decode(w, nt, bi, bj, h);
        const bool diag = (bi == bj);
        const size_t hoff1 = (size_t)(bj * 2 + 1) * CT + h * 8192;

        __syncthreads();        // previous item's srm reads complete
        if (tid < 128) {
            srm_bi[tid] = 0u;
            sCbi[tid]  = g_C[bi * TILE + tid];
            sn1bi[tid] = g_n1[bi * TILE + tid];
            sn2bi[tid] = g_n2[bi * TILE + tid];
        } else if (tid < 192) {
            int t = tid - 128;
            srm_bjH[t] = 0u;
            sCbjH[t]  = g_C[bj * TILE + h * 64 + t];
            sn1bjH[t] = g_n1[bj * TILE + h * 64 + t];
            sn2bjH[t] = g_n2[bj * TILE + h * 64 + t];
        } else if (tid == 255) {
            s_w = (int)atomicAdd(&g_work, 1u);          // ticket for NEXT item
        }

        float sum = 0.f;
        float acc1[2][4][4], acc2[2][4][4];
#pragma unroll
        for (int mf = 0; mf < 2; mf++)
#pragma unroll
            for (int nf = 0; nf < 4; nf++)
#pragma unroll
                for (int e = 0; e < 4; e++) { acc1[mf][nf][e] = 0.f; acc2[mf][nf][e] = 0.f; }

        CP_WAIT1();             // g0 ready
        __syncthreads();        // (also makes s_w visible to all)
        const int wn_next = s_w;

        // ---- phase1 pipelined ----
        group4(OPS + P1_AHI, OPS + P1_ALO, OPS + P1_B1H, OPS + P1_B1L, 0,
               arow, akoff, brow, bkoff, acc1);
        __syncthreads();
        cpa(OPS + P1_B1H, g_img_p1h + hoff1, 8192, tid);
        cpa(OPS + P1_B1L, g_img_p1l + hoff1, 8192, tid);
        CP_COMMIT();                                                // g2
        group4(OPS + P1_AHI, OPS + P1_ALO, OPS + P1_B2H, OPS + P1_B2L, 0,
               arow, akoff, brow, bkoff, acc2);
        __syncthreads();
        cpa(OPS + P1_B2H, g_img_p2h + hoff1, 8192, tid);
        cpa(OPS + P1_B2L, g_img_p2l + hoff1, 8192, tid);
        CP_COMMIT();                                                // g3
        CP_WAIT1();
        __syncthreads();
        group4(OPS + P1_AHI, OPS + P1_ALO, OPS + P1_B1H, OPS + P1_B1L, 64,
               arow, akoff, brow, bkoff, acc1);
        CP_WAIT0();
        __syncthreads();
        group4(OPS + P1_AHI, OPS + P1_ALO, OPS + P1_B2H, OPS + P1_B2L, 64,
               arow, akoff, brow, bkoff, acc2);
        __syncthreads();        // all phase1 operand reads done

        if (diag) {
            // prefetch next item's prologue; overlap epilogues/publish
            if (wn_next < nwork) {
                int nbi, nbj, nh; decode(wn_next, nt, nbi, nbj, nh);
                load_item(OPS, nbi, nbj, nh, tid);
            }
            epi_normal(acc1, sCbi, sn1bjH, wm, wn, qr, qc, l, true,
                       bi * TILE, bj * TILE + h * 64, srm_bi, sum);
            epi_normal(acc2, sCbi, sn2bjH, wm, wn, qr, qc, l, true,
                       bi * TILE, bj * TILE + h * 64, srm_bi, sum);
        } else {
            // phase2 buf0 prefetch, overlap phase1 epilogues
            const size_t hoff0 = (size_t)(bj * 2 + 0) * CT + h * 8192;
            cpa(OPS + P2_BUF(0) + P2_A2H, g_img_p1h + hoff0, 8192, tid);
            cpa(OPS + P2_BUF(0) + P2_A2L, g_img_p1l + hoff0, 8192, tid);
            cpa(OPS + P2_BUF(0) + P2_B2H, g_img_p2h + (size_t)(bi * 2 + 0) * CT, CT, tid);
            cpa(OPS + P2_BUF(0) + P2_B2L, g_img_p2l + (size_t)(bi * 2 + 0) * CT, CT, tid);
            CP_COMMIT();

            epi_normal(acc1, sCbi, sn1bjH, wm, wn, qr, qc, l, false,
                       bi * TILE, bj * TILE + h * 64, srm_bi, sum);
            epi_trans(acc1, sCbjH, sn1bi, wm, wn, qr, qc, l, srm_bjH, sum);
            epi_normal(acc2, sCbi, sn2bjH, wm, wn, qr, qc, l, false,
                       bi * TILE, bj * TILE + h * 64, srm_bi, sum);

            float accb[2][4][4];
#pragma unroll
            for (int mf = 0; mf < 2; mf++)
#pragma unroll
                for (int nf = 0; nf < 4; nf++)
#pragma unroll
                    for (int e = 0; e < 4; e++) accb[mf][nf][e] = 0.f;

            CP_WAIT0();
            __syncthreads();
            cpa(OPS + P2_BUF(1) + P2_A2H, g_img_p1h + hoff1, 8192, tid);
            cpa(OPS + P2_BUF(1) + P2_A2L, g_img_p1l + hoff1, 8192, tid);
            cpa(OPS + P2_BUF(1) + P2_B2H, g_img_p2h + (size_t)(bi * 2 + 1) * CT, CT, tid);
            cpa(OPS + P2_BUF(1) + P2_B2L, g_img_p2l + (size_t)(bi * 2 + 1) * CT, CT, tid);
            CP_COMMIT();

            group4(OPS + P2_BUF(0) + P2_A2H, OPS + P2_BUF(0) + P2_A2L,
                   OPS + P2_BUF(0) + P2_B2H, OPS + P2_BUF(0) + P2_B2L, 0,
                   arow2, akoff, brow2, bkoff, accb);
            CP_WAIT0();
            __syncthreads();
            group4(OPS + P2_BUF(1) + P2_A2H, OPS + P2_BUF(1) + P2_A2L,
                   OPS + P2_BUF(1) + P2_B2H, OPS + P2_BUF(1) + P2_B2L, 0,
                   arow2, akoff, brow2, bkoff, accb);
            __syncthreads();    // all phase2 operand reads done

            // prefetch next item's prologue; overlap phase2 epilogue/publish
            if (wn_next < nwork) {
                int nbi, nbj, nh; decode(wn_next, nt, nbi, nbj, nh);
                load_item(OPS, nbi, nbj, nh, tid);
            }
            epi_normal(accb, sCbjH, sn2bi, wm2, wn2, qr, qc, l, false, 0, 0, srm_bjH, sum);
        }

        // ---- publish this item ----
#pragma unroll
        for (int m = 16; m; m >>= 1) sum += __shfl_xor_sync(0xffffffffu, sum, m);
        if (l == 0) ssum[wid] = sum;
        __syncthreads();
        if (tid < 128)
            atomicMax(&g_rowmax[bi * TILE + tid], srm_bi[tid]);
        else if (tid < 192)
            atomicMax(&g_rowmax[bj * TILE + h * 64 + (tid - 128)], srm_bjH[tid - 128]);
        if (tid == 0) {
            float t = 0.f;
#pragma unroll
            for (int ww = 0; ww < 8; ww++) t += ssum[ww];
            g_partial[w] = t;
        }
        w = wn_next;
    }

    // ---- CTA done; last CTA finalizes ----
    __threadfence();
    __shared__ unsigned int s_last;
    if (tid == 0) s_last = (atomicAdd(&g_done, 1u) == (unsigned)(gridDim.x - 1)) ? 1u : 0u;
    __syncthreads();
    if (!s_last) return;
    __threadfence();

    double smax = 0.0, ssumd = 0.0;
    for (int i = tid; i < n; i += 256) {
        smax += (double)__uint_as_float(g_rowmax[i]);
        g_rowmax[i] = 0u;
    }
    for (int i = tid; i < nwork; i += 256) ssumd += (double)g_partial[i];
#pragma unroll
    for (int m = 16; m; m >>= 1) {
        smax  += __shfl_xor_sync(0xffffffffu, smax, m);
        ssumd += __shfl_xor_sync(0xffffffffu, ssumd, m);
    }
    __shared__ double d1[8], d2[8];
    if (l == 0) { d1[wid] = smax; d2[wid] = ssumd; }
    __syncthreads();
    if (tid == 0) {
        double t1 = 0.0, t2 = 0.0;
#pragma unroll
        for (int ww = 0; ww < 8; ww++) { t1 += d1[ww]; t2 += d2[ww]; }
        out[0] = (float)(t1 / (double)n);
        out[1] = (float)(t2 / (2.0 * (double)n * (double)(n - 1)));
        g_work = 0u;            // reset for graph replay
        g_done = 0u;
    }
}

extern "C" void kernel_launch(void* const* d_in, const int* in_sizes, int n_in,
                              void* d_out, int out_size) {
    const float* p1 = (const float*)d_in[0];
    const float* p2 = (const float*)d_in[1];
    float* out = (float*)d_out;
    const int n = in_sizes[0] / DIM;            // 4096
    const int nt = n / TILE;                    // 32
    const int nwork = nt * (nt + 1);            // 1056 half-pairs

    int nsm = 148;
    cudaDeviceGetAttribute(&nsm, cudaDevAttrMultiProcessorCount, 0);

    cudaFuncSetAttribute(triplet_persist_kernel,
                         cudaFuncAttributeMaxDynamicSharedMemorySize, SMEM_TOTAL);

    prep_kernel<<<n / 8, 256>>>(p1, p2, n);
    triplet_persist_kernel<<<nsm * 2, 256, SMEM_TOTAL>>>(out, n, nt, nwork);
}

// round 10
// speedup vs baseline: 3.5005x; 1.2350x over previous
#include <cuda_runtime.h>
#include <cuda_fp16.h>
#include <cstdint>

#define MARGIN 0.3f
#define DIM  128
#define TILE 128
#define MAXN 4096
#define MAXT (MAXN / TILE)
#define MAXPAIR (MAXT * (MAXT + 1) / 2)
#define CT   16384                 // image chunk tile: 128 rows x 64 fp16 cols (SW128)

// ---- dynamic smem layout (bytes) ----
#define SM_CBI   0                 // 128 f
#define SM_N1BI  512
#define SM_N2BI  1024
#define SM_CBJH  1536              // 64 f
#define SM_N1BJH 1792
#define SM_N2BJH 2048
#define SM_RMI   2304              // 128 u
#define SM_RMJH  2816              // 64 u
#define SM_SSUM  3072              // 8 f
#define SM_OPS   4096              // 80KB operand region, 1024-aligned
#define SMEM_TOTAL (SM_OPS + 80 * 1024)

// phase1: A hi full-K [0,32K) (c0,c1); B chunk buffers [32K,64K)
#define P1_AH  0
#define P1_B1H (32 * 1024)
#define P1_B1L (40 * 1024)
#define P1_B2H (48 * 1024)
#define P1_B2L (56 * 1024)
// phase2 double buffer: buf c at c*40K: A2H 8K, B2H 16K, B2L 16K
#define P2_BUF(c) ((c) * 40 * 1024)
#define P2_A2H 0
#define P2_B2H (8 * 1024)
#define P2_B2L (24 * 1024)

__device__ float g_n1[MAXN], g_n2[MAXN], g_C[MAXN];
__device__ unsigned int g_rowmax[MAXN];      // zero at load; finalizer re-zeros
__device__ float g_partial[2 * MAXPAIR];
__device__ unsigned int g_work;              // work ticket; finalizer re-zeros
__device__ unsigned int g_done;              // CTA done counter; finalizer re-zeros

// pre-swizzled fp16 hi/lo images: [tile][chunk][16KB]
__device__ __align__(16) unsigned char g_img_p1h[MAXT * 2 * CT];
__device__ __align__(16) unsigned char g_img_p1l[MAXT * 2 * CT];
__device__ __align__(16) unsigned char g_img_p2h[MAXT * 2 * CT];
__device__ __align__(16) unsigned char g_img_p2l[MAXT * 2 * CT];

__device__ __forceinline__ uint32_t smem_u32(const void* p) {
    uint32_t a;
    asm("{ .reg .u64 t; cvta.to.shared.u64 t, %1; cvt.u32.u64 %0, t; }" : "=r"(a) : "l"(p));
    return a;
}
__device__ __forceinline__ int swz(int row, int kc) {
    int b = row * 128 + kc * 2;
    return b ^ ((b >> 3) & 0x70);
}
__device__ __forceinline__ uint32_t taddrA(uint32_t base0, int row, int kcol) {
    return base0 + ((kcol >> 6) << 14) + swz(row, kcol & 63);
}
__device__ __forceinline__ void ldsm4(uint32_t addr, uint32_t r[4]) {
    asm volatile("ldmatrix.sync.aligned.m8n8.x4.shared.b16 {%0,%1,%2,%3}, [%4];"
                 : "=r"(r[0]), "=r"(r[1]), "=r"(r[2]), "=r"(r[3]) : "r"(addr));
}
__device__ __forceinline__ void cp16(uint32_t saddr, const void* g) {
    asm volatile("cp.async.cg.shared.global [%0], [%1], 16;" :: "r"(saddr), "l"(g));
}
#define CP_COMMIT() asm volatile("cp.async.commit_group;" ::: "memory")
#define CP_WAIT0()  asm volatile("cp.async.wait_group 0;" ::: "memory")
#define CP_WAIT1()  asm volatile("cp.async.wait_group 1;" ::: "memory")

#define MMA(d, a, b)                                                               \
    asm volatile("mma.sync.aligned.m16n8k16.row.col.f32.f16.f16.f32 "              \
                 "{%0,%1,%2,%3},{%4,%5,%6,%7},{%8,%9},{%0,%1,%2,%3};"              \
                 : "+f"((d)[0]), "+f"((d)[1]), "+f"((d)[2]), "+f"((d)[3])          \
                 : "r"((a)[0]), "r"((a)[1]), "r"((a)[2]), "r"((a)[3]),             \
                   "r"((b)[0]), "r"((b)[1]))

union HU { __half2 h; uint32_t u; };

__device__ __forceinline__ void cpa(uint32_t sdst, const unsigned char* gsrc, int bytes, int tid) {
    for (int t = tid * 16; t < bytes; t += 4096) cp16(sdst + t, gsrc + t);
}

__device__ __forceinline__ void decode(int w, int nt, int& bi, int& bj, int& h) {
    int pairid = w >> 1;
    h = w & 1;
    bi = 0;
    int rem = pairid;
    while (rem >= nt - bi) { rem -= (nt - bi); bi++; }
    bj = bi + rem;
}

// phase1 prologue loads for item (bi,bj,h): g0 = A-hi-c0 + B-c0, g1 = A-hi-c1
__device__ __forceinline__ void load_item(uint32_t OPS, int bi, int bj, int h, int tid) {
    size_t hoff0 = (size_t)(bj * 2 + 0) * CT + h * 8192;
    cpa(OPS + P1_AH, g_img_p1h + (size_t)(bi * 2 + 0) * CT, CT, tid);
    cpa(OPS + P1_B1H, g_img_p1h + hoff0, 8192, tid);
    cpa(OPS + P1_B1L, g_img_p1l + hoff0, 8192, tid);
    cpa(OPS + P1_B2H, g_img_p2h + hoff0, 8192, tid);
    cpa(OPS + P1_B2L, g_img_p2l + hoff0, 8192, tid);
    CP_COMMIT();                                                   // g0
    cpa(OPS + P1_AH + CT, g_img_p1h + (size_t)(bi * 2 + 1) * CT, CT, tid);
    CP_COMMIT();                                                   // g1
}

// 4 ksteps of one gram: A hi (2-chunk region) x B (hi+lo, single chunk) — 16 MMA, 6 ldsm per kstep
__device__ __forceinline__ void group4(
    uint32_t AH, uint32_t BH, uint32_t BL, int kAbase,
    int arow, int akoff, int brow, int bkoff, float (&acc)[2][4][4])
{
#pragma unroll
    for (int ks = 0; ks < 4; ks++) {
        const int kA = kAbase + ks * 16;
        const int kB = ks * 16;
        uint32_t ah[2][4];
#pragma unroll
        for (int mf = 0; mf < 2; mf++)
            ldsm4(taddrA(AH, arow + mf * 16, kA + akoff), ah[mf]);
        uint32_t bh[4][2], bl[4][2];
#pragma unroll
        for (int np = 0; np < 2; np++) {
            uint32_t t4[4];
            ldsm4(BH + swz(brow + np * 16, kB + bkoff), t4);
            bh[2*np][0]=t4[0]; bh[2*np][1]=t4[1]; bh[2*np+1][0]=t4[2]; bh[2*np+1][1]=t4[3];
            ldsm4(BL + swz(brow + np * 16, kB + bkoff), t4);
            bl[2*np][0]=t4[0]; bl[2*np][1]=t4[1]; bl[2*np+1][0]=t4[2]; bl[2*np+1][1]=t4[3];
        }
#pragma unroll
        for (int mf = 0; mf < 2; mf++)
#pragma unroll
            for (int nf = 0; nf < 4; nf++) {
                MMA(acc[mf][nf], ah[mf], bh[nf]);
                MMA(acc[mf][nf], ah[mf], bl[nf]);
            }
    }
}

__device__ __forceinline__ void epi_normal(
    float (&acc)[2][4][4], const float* Crow, const float* ncol,
    int wm, int wn, int qr, int qc, int l, bool dz, int rbase, int cbase,
    unsigned int* srm, float& sum)
{
    float Cr[2][2], nc[4][2];
#pragma unroll
    for (int mf = 0; mf < 2; mf++) {
        int r0 = wm * 32 + mf * 16 + qr;
        Cr[mf][0] = Crow[r0]; Cr[mf][1] = Crow[r0 + 8];
    }
#pragma unroll
    for (int nf = 0; nf < 4; nf++) {
        int c0 = wn * 32 + nf * 8 + qc;
        nc[nf][0] = ncol[c0]; nc[nf][1] = ncol[c0 + 1];
    }
    float rmax[2][2] = {{0.f, 0.f}, {0.f, 0.f}};
#pragma unroll
    for (int mf = 0; mf < 2; mf++)
#pragma unroll
        for (int nf = 0; nf < 4; nf++)
#pragma unroll
            for (int e = 0; e < 4; e++) {
                int rr = e >> 1, cc = e & 1;
                float v = fmaxf(Cr[mf][rr] - nc[nf][cc] + 2.f * acc[mf][nf][e], 0.f);
                if (dz) {
                    int rl = rbase + wm * 32 + mf * 16 + qr + rr * 8;
                    int cl = cbase + wn * 32 + nf * 8 + qc + cc;
                    if (rl == cl) v = 0.f;
                }
                sum += v;
                rmax[mf][rr] = fmaxf(rmax[mf][rr], v);
            }
#pragma unroll
    for (int m = 1; m <= 2; m <<= 1)
#pragma unroll
        for (int mf = 0; mf < 2; mf++) {
            rmax[mf][0] = fmaxf(rmax[mf][0], __shfl_xor_sync(0xffffffffu, rmax[mf][0], m));
            rmax[mf][1] = fmaxf(rmax[mf][1], __shfl_xor_sync(0xffffffffu, rmax[mf][1], m));
        }
    if ((l & 3) == 0) {
#pragma unroll
        for (int mf = 0; mf < 2; mf++) {
            atomicMax(&srm[wm * 32 + mf * 16 + qr],     __float_as_uint(rmax[mf][0]));
            atomicMax(&srm[wm * 32 + mf * 16 + qr + 8], __float_as_uint(rmax[mf][1]));
        }
    }
}

__device__ __forceinline__ void epi_trans(
    float (&acc)[2][4][4], const float* Ccol, const float* nrow,
    int wm, int wn, int qr, int qc, int l,
    unsigned int* srm, float& sum)
{
    float Ct[4][2], nr[2][2];
#pragma unroll
    for (int nf = 0; nf < 4; nf++) {
        int c0 = wn * 32 + nf * 8 + qc;
        Ct[nf][0] = Ccol[c0]; Ct[nf][1] = Ccol[c0 + 1];
    }
#pragma unroll
    for (int mf = 0; mf < 2; mf++) {
        int r0 = wm * 32 + mf * 16 + qr;
        nr[mf][0] = nrow[r0]; nr[mf][1] = nrow[r0 + 8];
    }
    float cmax[4][2] = {{0.f,0.f},{0.f,0.f},{0.f,0.f},{0.f,0.f}};
#pragma unroll
    for (int mf = 0; mf < 2; mf++)
#pragma unroll
        for (int nf = 0; nf < 4; nf++)
#pragma unroll
            for (int e = 0; e < 4; e++) {
                int rr = e >> 1, cc = e & 1;
                float v = fmaxf(Ct[nf][cc] - nr[mf][rr] + 2.f * acc[mf][nf][e], 0.f);
                sum += v;
                cmax[nf][cc] = fmaxf(cmax[nf][cc], v);
            }
#pragma unroll
    for (int m = 4; m <= 16; m <<= 1)
#pragma unroll
        for (int nf = 0; nf < 4; nf++) {
            cmax[nf][0] = fmaxf(cmax[nf][0], __shfl_xor_sync(0xffffffffu, cmax[nf][0], m));
            cmax[nf][1] = fmaxf(cmax[nf][1], __shfl_xor_sync(0xffffffffu, cmax[nf][1], m));
        }
    if (l < 4) {
#pragma unroll
        for (int nf = 0; nf < 4; nf++) {
            int c0 = wn * 32 + nf * 8 + qc;
            atomicMax(&srm[c0],     __float_as_uint(cmax[nf][0]));
            atomicMax(&srm[c0 + 1], __float_as_uint(cmax[nf][1]));
        }
    }
}

// ---- prep: norms/C + pre-swizzled fp16 hi/lo images ----
__global__ void __launch_bounds__(256)
prep_kernel(const float* __restrict__ p1, const float* __restrict__ p2, int n) {
    int row = blockIdx.x * 8 + (threadIdx.x >> 5);
    int lane = threadIdx.x & 31;
    if (row >= n) return;
    float4 a = ((const float4*)(p1 + (size_t)row * DIM))[lane];
    float4 b = ((const float4*)(p2 + (size_t)row * DIM))[lane];

    float n1 = a.x*a.x + a.y*a.y + a.z*a.z + a.w*a.w;
    float n2 = b.x*b.x + b.y*b.y + b.z*b.z + b.w*b.w;
    float dx = a.x-b.x, dy = a.y-b.y, dz = a.z-b.z, dw = a.w-b.w;
    float dap = dx*dx + dy*dy + dz*dz + dw*dw;
#pragma unroll
    for (int m = 16; m; m >>= 1) {
        n1 += __shfl_xor_sync(0xffffffffu, n1, m);
        n2 += __shfl_xor_sync(0xffffffffu, n2, m);
        dap += __shfl_xor_sync(0xffffffffu, dap, m);
    }
    if (lane == 0) {
        g_n1[row] = n1; g_n2[row] = n2; g_C[row] = dap - n1 + MARGIN;
    }

    int tile = row >> 7, lr = row & 127;
    int c4 = lane * 4, chunk = c4 >> 6, lc = c4 & 63;
    size_t off = (size_t)(tile * 2 + chunk) * CT + swz(lr, lc);

    HU h0, h1, l0, l1;
    h0.h = __floats2half2_rn(a.x, a.y);
    h1.h = __floats2half2_rn(a.z, a.w);
    l0.h = __floats2half2_rn(a.x - __low2float(h0.h), a.y - __high2float(h0.h));
    l1.h = __floats2half2_rn(a.z - __low2float(h1.h), a.w - __high2float(h1.h));
    *(uint2*)(g_img_p1h + off) = make_uint2(h0.u, h1.u);
    *(uint2*)(g_img_p1l + off) = make_uint2(l0.u, l1.u);

    h0.h = __floats2half2_rn(b.x, b.y);
    h1.h = __floats2half2_rn(b.z, b.w);
    l0.h = __floats2half2_rn(b.x - __low2float(h0.h), b.y - __high2float(h0.h));
    l1.h = __floats2half2_rn(b.z - __low2float(h1.h), b.w - __high2float(h1.h));
    *(uint2*)(g_img_p2h + off) = make_uint2(h0.u, h1.u);
    *(uint2*)(g_img_p2l + off) = make_uint2(l0.u, l1.u);
}

// ---- main: persistent CTAs, dynamic work stealing, cross-item prefetch ----
__global__ void __launch_bounds__(256, 2)
triplet_persist_kernel(float* __restrict__ out, int n, int nt, int nwork) {
    extern __shared__ char smem[];
    const uint32_t sbase = smem_u32(smem);
    const int tid = threadIdx.x;
    const int wid = tid >> 5;
    const int l   = tid & 31;

    float* sCbi   = (float*)(smem + SM_CBI);
    float* sn1bi  = (float*)(smem + SM_N1BI);
    float* sn2bi  = (float*)(smem + SM_N2BI);
    float* sCbjH  = (float*)(smem + SM_CBJH);
    float* sn1bjH = (float*)(smem + SM_N1BJH);
    float* sn2bjH = (float*)(smem + SM_N2BJH);
    unsigned int* srm_bi  = (unsigned int*)(smem + SM_RMI);
    unsigned int* srm_bjH = (unsigned int*)(smem + SM_RMJH);
    float* ssum = (float*)(smem + SM_SSUM);
    const uint32_t OPS = sbase + SM_OPS;

    __shared__ int s_w;

    const int wm = wid & 3;
    const int wn = wid >> 2;
    const int qr = l >> 2;
    const int qc = (l & 3) * 2;
    const int arow = wm * 32 + (l & 7) + ((l >> 3) & 1) * 8;
    const int akoff = (l >> 4) * 8;
    const int brow = wn * 32 + (l & 7) + ((l >> 4) << 3);
    const int bkoff = ((l >> 3) & 1) * 8;
    const int wm2 = wid & 1;
    const int wn2 = wid >> 1;
    const int arow2 = wm2 * 32 + (l & 7) + ((l >> 3) & 1) * 8;
    const int brow2 = wn2 * 32 + (l & 7) + ((l >> 4) << 3);

    if (tid == 0) s_w = (int)atomicAdd(&g_work, 1u);
    __syncthreads();
    int w = s_w;
    if (w < nwork) {
        int bi, bj, h; decode(w, nt, bi, bj, h);
        load_item(OPS, bi, bj, h, tid);                 // g0, g1 outstanding
    }

    while (w < nwork) {
        int bi, bj, h; decode(w, nt, bi, bj, h);
        const bool diag = (bi == bj);
        const size_t hoff1 = (size_t)(bj * 2 + 1) * CT + h * 8192;

        __syncthreads();
        if (tid < 128) {
            srm_bi[tid] = 0u;
            sCbi[tid]  = g_C[bi * TILE + tid];
            sn1bi[tid] = g_n1[bi * TILE + tid];
            sn2bi[tid] = g_n2[bi * TILE + tid];
        } else if (tid < 192) {
            int t = tid - 128;
            srm_bjH[t] = 0u;
            sCbjH[t]  = g_C[bj * TILE + h * 64 + t];
            sn1bjH[t] = g_n1[bj * TILE + h * 64 + t];
            sn2bjH[t] = g_n2[bj * TILE + h * 64 + t];
        } else if (tid == 255) {
            s_w = (int)atomicAdd(&g_work, 1u);          // ticket for NEXT item
        }

        float sum = 0.f;
        float acc1[2][4][4], acc2[2][4][4];
#pragma unroll
        for (int mf = 0; mf < 2; mf++)
#pragma unroll
            for (int nf = 0; nf < 4; nf++)
#pragma unroll
                for (int e = 0; e < 4; e++) { acc1[mf][nf][e] = 0.f; acc2[mf][nf][e] = 0.f; }

        CP_WAIT1();             // g0 ready
        __syncthreads();        // (also publishes s_w)
        const int wn_next = s_w;

        // ---- phase1 pipelined ----
        group4(OPS + P1_AH, OPS + P1_B1H, OPS + P1_B1L, 0,
               arow, akoff, brow, bkoff, acc1);
        __syncthreads();
        cpa(OPS + P1_B1H, g_img_p1h + hoff1, 8192, tid);
        cpa(OPS + P1_B1L, g_img_p1l + hoff1, 8192, tid);
        CP_COMMIT();                                                // g2
        group4(OPS + P1_AH, OPS + P1_B2H, OPS + P1_B2L, 0,
               arow, akoff, brow, bkoff, acc2);
        __syncthreads();
        cpa(OPS + P1_B2H, g_img_p2h + hoff1, 8192, tid);
        cpa(OPS + P1_B2L, g_img_p2l + hoff1, 8192, tid);
        CP_COMMIT();                                                // g3
        CP_WAIT1();
        __syncthreads();
        group4(OPS + P1_AH, OPS + P1_B1H, OPS + P1_B1L, 64,
               arow, akoff, brow, bkoff, acc1);
        CP_WAIT0();
        __syncthreads();
        group4(OPS + P1_AH, OPS + P1_B2H, OPS + P1_B2L, 64,
               arow, akoff, brow, bkoff, acc2);
        __syncthreads();        // all phase1 operand reads done

        if (diag) {
            if (wn_next < nwork) {
                int nbi, nbj, nh; decode(wn_next, nt, nbi, nbj, nh);
                load_item(OPS, nbi, nbj, nh, tid);
            }
            epi_normal(acc1, sCbi, sn1bjH, wm, wn, qr, qc, l, true,
                       bi * TILE, bj * TILE + h * 64, srm_bi, sum);
            epi_normal(acc2, sCbi, sn2bjH, wm, wn, qr, qc, l, true,
                       bi * TILE, bj * TILE + h * 64, srm_bi, sum);
        } else {
            const size_t hoff0 = (size_t)(bj * 2 + 0) * CT + h * 8192;
            cpa(OPS + P2_BUF(0) + P2_A2H, g_img_p1h + hoff0, 8192, tid);
            cpa(OPS + P2_BUF(0) + P2_B2H, g_img_p2h + (size_t)(bi * 2 + 0) * CT, CT, tid);
            cpa(OPS + P2_BUF(0) + P2_B2L, g_img_p2l + (size_t)(bi * 2 + 0) * CT, CT, tid);
            CP_COMMIT();

            epi_normal(acc1, sCbi, sn1bjH, wm, wn, qr, qc, l, false,
                       bi * TILE, bj * TILE + h * 64, srm_bi, sum);
            epi_trans(acc1, sCbjH, sn1bi, wm, wn, qr, qc, l, srm_bjH, sum);
            epi_normal(acc2, sCbi, sn2bjH, wm, wn, qr, qc, l, false,
                       bi * TILE, bj * TILE + h * 64, srm_bi, sum);

            float accb[2][4][4];
#pragma unroll
            for (int mf = 0; mf < 2; mf++)
#pragma unroll
                for (int nf = 0; nf < 4; nf++)
#pragma unroll
                    for (int e = 0; e < 4; e++) accb[mf][nf][e] = 0.f;

            CP_WAIT0();
            __syncthreads();
            cpa(OPS + P2_BUF(1) + P2_A2H, g_img_p1h + hoff1, 8192, tid);
            cpa(OPS + P2_BUF(1) + P2_B2H, g_img_p2h + (size_t)(bi * 2 + 1) * CT, CT, tid);
            cpa(OPS + P2_BUF(1) + P2_B2L, g_img_p2l + (size_t)(bi * 2 + 1) * CT, CT, tid);
            CP_COMMIT();

            group4(OPS + P2_BUF(0) + P2_A2H, OPS + P2_BUF(0) + P2_B2H,
                   OPS + P2_BUF(0) + P2_B2L, 0, arow2, akoff, brow2, bkoff, accb);
            CP_WAIT0();
            __syncthreads();
            group4(OPS + P2_BUF(1) + P2_A2H, OPS + P2_BUF(1) + P2_B2H,
                   OPS + P2_BUF(1) + P2_B2L, 0, arow2, akoff, brow2, bkoff, accb);
            __syncthreads();    // all phase2 operand reads done

            if (wn_next < nwork) {
                int nbi, nbj, nh; decode(wn_next, nt, nbi, nbj, nh);
                load_item(OPS, nbi, nbj, nh, tid);
            }
            epi_normal(accb, sCbjH, sn2bi, wm2, wn2, qr, qc, l, false, 0, 0, srm_bjH, sum);
        }

        // ---- publish this item ----
#pragma unroll
        for (int m = 16; m; m >>= 1) sum += __shfl_xor_sync(0xffffffffu, sum, m);
        if (l == 0) ssum[wid] = sum;
        __syncthreads();
        if (tid < 128)
            atomicMax(&g_rowmax[bi * TILE + tid], srm_bi[tid]);
        else if (tid < 192)
            atomicMax(&g_rowmax[bj * TILE + h * 64 + (tid - 128)], srm_bjH[tid - 128]);
        if (tid == 0) {
            float t = 0.f;
#pragma unroll
            for (int ww = 0; ww < 8; ww++) t += ssum[ww];
            g_partial[w] = t;
        }
        w = wn_next;
    }

    // ---- CTA done; last CTA finalizes ----
    __threadfence();
    __shared__ unsigned int s_last;
    if (tid == 0) s_last = (atomicAdd(&g_done, 1u) == (unsigned)(gridDim.x - 1)) ? 1u : 0u;
    __syncthreads();
    if (!s_last) return;
    __threadfence();

    double smax = 0.0, ssumd = 0.0;
    for (int i = tid; i < n; i += 256) {
        smax += (double)__uint_as_float(g_rowmax[i]);
        g_rowmax[i] = 0u;
    }
    for (int i = tid; i < nwork; i += 256) ssumd += (double)g_partial[i];
#pragma unroll
    for (int m = 16; m; m >>= 1) {
        smax  += __shfl_xor_sync(0xffffffffu, smax, m);
        ssumd += __shfl_xor_sync(0xffffffffu, ssumd, m);
    }
    __shared__ double d1[8], d2[8];
    if (l == 0) { d1[wid] = smax; d2[wid] = ssumd; }
    __syncthreads();
    if (tid == 0) {
        double t1 = 0.0, t2 = 0.0;
#pragma unroll
        for (int ww = 0; ww < 8; ww++) { t1 += d1[ww]; t2 += d2[ww]; }
        out[0] = (float)(t1 / (double)n);
        out[1] = (float)(t2 / (2.0 * (double)n * (double)(n - 1)));
        g_work = 0u;
        g_done = 0u;
    }
}

extern "C" void kernel_launch(void* const* d_in, const int* in_sizes, int n_in,
                              void* d_out, int out_size) {
    const float* p1 = (const float*)d_in[0];
    const float* p2 = (const float*)d_in[1];
    float* out = (float*)d_out;
    const int n = in_sizes[0] / DIM;            // 4096
    const int nt = n / TILE;                    // 32
    const int nwork = nt * (nt + 1);            // 1056 half-pairs

    int nsm = 148;
    cudaDeviceGetAttribute(&nsm, cudaDevAttrMultiProcessorCount, 0);

    cudaFuncSetAttribute(triplet_persist_kernel,
                         cudaFuncAttributeMaxDynamicSharedMemorySize, SMEM_TOTAL);

    prep_kernel<<<n / 8, 256>>>(p1, p2, n);
    triplet_persist_kernel<<<nsm * 2, 256, SMEM_TOTAL>>>(out, n, nt, nwork);
}